// round 4
// baseline (speedup 1.0000x reference)
#include <cuda_runtime.h>
#include <cstdint>
#include <math.h>

// ---------------- Problem constants ----------------
constexpr int Bb   = 8;
constexpr int Dd   = 60;
constexpr int NP   = 1024;
constexpr int KNN  = 20;
constexpr int P    = Bb * NP;        // 8192 points
constexpr int M4   = P * KNN;        // 163840 graph-feature rows
constexpr float EPSV  = 1e-5f;
constexpr float SLOPE = 0.2f;

#define NEG_INF (__int_as_float(0xff800000))

// ---------------- Device scratch (static allocs are allowed) ----------------
__device__ float g_xx[P];
__device__ float g_pd[(size_t)Bb * NP * NP];           // 32 MB
__device__ int   g_idx[M4];
__device__ float g_q[(size_t)P * 64];                  // A @ x (per neighbor)
__device__ float g_p[(size_t)P * 64];                  // (B-A) @ x (per center)
__device__ float g_t1[(size_t)M4 * 64];                // stage preacts
__device__ float g_t2[(size_t)M4 * 64];
__device__ float g_t3[(size_t)M4 * 128];
__device__ float g_t4[(size_t)M4 * 256];
__device__ float g_cat[(size_t)P * 512];               // concat(x1..x4), post-activation
__device__ float g_t5[(size_t)P * 256];
__device__ float g_t6[(size_t)P * 1024];
__device__ float g_ps[1 << 20];                        // partial sums
__device__ float g_pq[1 << 20];                        // partial sumsq
__device__ float g_sc[6][1024];                        // BN scale  a = g*rsqrt(var+eps)
__device__ float g_sh[6][1024];                        // BN shift  b = be - mean*a

// ---------------- xx[b,n] = sum_d x^2 ----------------
__global__ void xx_kernel(const float* __restrict__ x) {
    int i = blockIdx.x * 256 + threadIdx.x;            // 0..8191
    int b = i >> 10, n = i & 1023;
    const float* xb = x + (size_t)b * Dd * NP + n;
    float s = 0.f;
#pragma unroll
    for (int d = 0; d < Dd; d++) { float v = xb[d * NP]; s += v * v; }
    g_xx[i] = s;
}

// ---------------- pd[b,n,m] = 2*dot(x_n, x_m) - xx_n - xx_m ----------------
__global__ void pd_kernel(const float* __restrict__ x) {
    int b  = blockIdx.z;
    int n0 = blockIdx.y * 64;
    int m0 = blockIdx.x * 64;
    __shared__ float Xa[Dd][64];
    __shared__ float Xb[Dd][64];
    const float* xb = x + (size_t)b * Dd * NP;
    for (int l = threadIdx.x; l < Dd * 64; l += 256) {
        int d = l >> 6, mm = l & 63;
        Xa[d][mm] = xb[d * NP + n0 + mm];
        Xb[d][mm] = xb[d * NP + m0 + mm];
    }
    __syncthreads();
    int tx = threadIdx.x & 15, ty = threadIdx.x >> 4;
    float acc[4][4] = {};
#pragma unroll
    for (int d = 0; d < Dd; d++) {
        float a[4], c[4];
#pragma unroll
        for (int i = 0; i < 4; i++) a[i] = Xa[d][ty * 4 + i];
#pragma unroll
        for (int j = 0; j < 4; j++) c[j] = Xb[d][tx * 4 + j];
#pragma unroll
        for (int i = 0; i < 4; i++)
#pragma unroll
            for (int j = 0; j < 4; j++) acc[i][j] += a[i] * c[j];
    }
#pragma unroll
    for (int i = 0; i < 4; i++) {
        int n = n0 + ty * 4 + i;
        float xn = g_xx[b * NP + n];
#pragma unroll
        for (int j = 0; j < 4; j++) {
            int m = m0 + tx * 4 + j;
            g_pd[((size_t)b << 20) + (size_t)n * NP + m] =
                2.f * acc[i][j] - xn - g_xx[b * NP + m];
        }
    }
}

// ---------------- top-k (k=20) indices per row via masked argmax ----------------
__global__ void topk_kernel() {
    int bn = blockIdx.x;                               // 8192
    const float* row = g_pd + (size_t)bn * NP;
    int tid = threadIdx.x;
    float v[4]; int mi[4];
#pragma unroll
    for (int i = 0; i < 4; i++) { mi[i] = i * 256 + tid; v[i] = row[mi[i]]; }
    __shared__ float sv[256];
    __shared__ int   si[256];
    for (int it = 0; it < KNN; it++) {
        float bv = v[0]; int bi = mi[0];
#pragma unroll
        for (int i = 1; i < 4; i++)
            if (v[i] > bv || (v[i] == bv && mi[i] < bi)) { bv = v[i]; bi = mi[i]; }
        sv[tid] = bv; si[tid] = bi;
        __syncthreads();
        for (int st = 128; st > 0; st >>= 1) {
            if (tid < st) {
                if (sv[tid + st] > sv[tid] ||
                    (sv[tid + st] == sv[tid] && si[tid + st] < si[tid])) {
                    sv[tid] = sv[tid + st]; si[tid] = si[tid + st];
                }
            }
            __syncthreads();
        }
        int w = si[0];
        if (tid == 0) g_idx[bn * KNN + it] = w;
#pragma unroll
        for (int i = 0; i < 4; i++) if (mi[i] == w) v[i] = NEG_INF;
        __syncthreads();
    }
}

// ---------------- q = A@x, p = (B-A)@x  (stage-1 weight split) ----------------
__global__ void qp_kernel(const float* __restrict__ x, const float* __restrict__ w1) {
    int b  = blockIdx.y;
    int m0 = blockIdx.x * 64;
    __shared__ float xs[Dd][64];
    __shared__ float ws[64][120];
    const float* xb = x + (size_t)b * Dd * NP;
    for (int l = threadIdx.x; l < Dd * 64; l += 256) {
        int d = l >> 6, m = l & 63;
        xs[d][m] = xb[d * NP + m0 + m];
    }
    for (int l = threadIdx.x; l < 64 * 120; l += 256) ws[l / 120][l % 120] = w1[l];
    __syncthreads();
    int tx = threadIdx.x & 15, ty = threadIdx.x >> 4;
    float qa[4][4] = {}, pa[4][4] = {};
#pragma unroll
    for (int d = 0; d < Dd; d++) {
        float wa[4], wb[4], xm[4];
#pragma unroll
        for (int i = 0; i < 4; i++) {
            wa[i] = ws[ty * 4 + i][d];
            wb[i] = ws[ty * 4 + i][60 + d] - wa[i];
        }
#pragma unroll
        for (int j = 0; j < 4; j++) xm[j] = xs[d][tx * 4 + j];
#pragma unroll
        for (int i = 0; i < 4; i++)
#pragma unroll
            for (int j = 0; j < 4; j++) {
                qa[i][j] += wa[i] * xm[j];
                pa[i][j] += wb[i] * xm[j];
            }
    }
#pragma unroll
    for (int i = 0; i < 4; i++)
#pragma unroll
        for (int j = 0; j < 4; j++) {
            int o = ty * 4 + i, m = m0 + tx * 4 + j;
            size_t base = ((size_t)b * NP + m) * 64 + o;
            g_q[base] = qa[i][j];
            g_p[base] = pa[i][j];
        }
}

// ---------------- t1[(b,n,j), o] = q[b, idx, o] + p[b, n, o] + b1[o] ----------------
__global__ void s1_kernel(const float* __restrict__ b1) {
    int row = blockIdx.x * 4 + (threadIdx.x >> 6);
    int c = threadIdx.x & 63;
    int b = row / (NP * KNN);
    int rem = row % (NP * KNN);
    int n = rem / KNN;
    int m = g_idx[row];
    float v = g_q[((size_t)b * NP + m) * 64 + c] +
              g_p[((size_t)b * NP + n) * 64 + c] + b1[c];
    g_t1[(size_t)row * 64 + c] = v;
}

// ---------------- deterministic per-channel stats: partial then finalize ----------------
__global__ void stats_partial(const float* __restrict__ t, int O, float* __restrict__ ps,
                              float* __restrict__ pq) {
    int r0 = blockIdx.x * 64;
    int tid = threadIdx.x;
    if (O <= 256) {
        int gsz = 256 / O;
        int c = tid % O;
        int slot = tid / O;
        float s = 0.f, q = 0.f;
        for (int r = r0 + slot; r < r0 + 64; r += gsz) {
            float v = t[(size_t)r * O + c];
            s += v; q += v * v;
        }
        __shared__ float ss[256], sq[256];
        ss[tid] = s; sq[tid] = q;
        __syncthreads();
        for (int st = 128; st >= O; st >>= 1) {
            if (tid < st) { ss[tid] += ss[tid + st]; sq[tid] += sq[tid + st]; }
            __syncthreads();
        }
        if (tid < O) {
            ps[(size_t)blockIdx.x * O + tid] = ss[tid];
            pq[(size_t)blockIdx.x * O + tid] = sq[tid];
        }
    } else {  // O == 1024
        float s[4] = {}, q[4] = {};
        for (int r = r0; r < r0 + 64; r++) {
            const float* tr = t + (size_t)r * 1024;
#pragma unroll
            for (int j = 0; j < 4; j++) {
                float v = tr[tid + 256 * j];
                s[j] += v; q[j] += v * v;
            }
        }
#pragma unroll
        for (int j = 0; j < 4; j++) {
            ps[(size_t)blockIdx.x * 1024 + tid + 256 * j] = s[j];
            pq[(size_t)blockIdx.x * 1024 + tid + 256 * j] = q[j];
        }
    }
}

__global__ void stats_finalize(int nb, int O, float cnt, int stage,
                               const float* __restrict__ g, const float* __restrict__ be) {
    int c = blockIdx.x * blockDim.x + threadIdx.x;
    if (c >= O) return;
    double s = 0.0, q = 0.0;
    for (int i = 0; i < nb; i++) {
        s += g_ps[(size_t)i * O + c];
        q += g_pq[(size_t)i * O + c];
    }
    double m = s / cnt;
    double v = q / cnt - m * m;
    float a = g[c] * rsqrtf((float)v + EPSV);
    g_sc[stage][c] = a;
    g_sh[stage][c] = be[c] - (float)m * a;
}

// ---------------- tiled fp32 GEMM: C[M,O] = act(A)[M,K] . W[O,K]^T + bias ----------------
// act = lrelu(bn) via per-k scale/shift when TRANS
template <int BM, int BN, int BK, int TM, int TN, bool TRANS>
__global__ __launch_bounds__(256) void gemm_kernel(
    const float* __restrict__ A, const float* __restrict__ W,
    const float* __restrict__ bias, const float* __restrict__ tsc,
    const float* __restrict__ tsh, float* __restrict__ C, int K, int NN) {
    __shared__ float As[BK][BM + 4];
    __shared__ float Ws[BK][BN + 4];
    int m0 = blockIdx.y * BM;
    int n0 = blockIdx.x * BN;
    int tid = threadIdx.x;
    int tx = tid % (BN / TN);
    int ty = tid / (BN / TN);
    float acc[TM][TN] = {};
    for (int k0 = 0; k0 < K; k0 += BK) {
        constexpr int AV = BM * BK / 4;
        for (int i = tid; i < AV; i += 256) {
            int r = i / (BK / 4);
            int kq = i % (BK / 4);
            float4 vv = *(const float4*)(A + (size_t)(m0 + r) * K + k0 + kq * 4);
            float vals[4] = {vv.x, vv.y, vv.z, vv.w};
#pragma unroll
            for (int e = 0; e < 4; e++) {
                float u = vals[e];
                if (TRANS) {
                    int kk = k0 + kq * 4 + e;
                    u = u * tsc[kk] + tsh[kk];
                    u = u >= 0.f ? u : SLOPE * u;
                }
                As[kq * 4 + e][r] = u;
            }
        }
        constexpr int WV = BN * BK / 4;
        for (int i = tid; i < WV; i += 256) {
            int r = i / (BK / 4);
            int kq = i % (BK / 4);
            float4 vv = *(const float4*)(W + (size_t)(n0 + r) * K + k0 + kq * 4);
            Ws[kq * 4 + 0][r] = vv.x;
            Ws[kq * 4 + 1][r] = vv.y;
            Ws[kq * 4 + 2][r] = vv.z;
            Ws[kq * 4 + 3][r] = vv.w;
        }
        __syncthreads();
#pragma unroll
        for (int k = 0; k < BK; k++) {
            float a[TM], b[TN];
#pragma unroll
            for (int i = 0; i < TM; i++) a[i] = As[k][ty * TM + i];
#pragma unroll
            for (int j = 0; j < TN; j++) b[j] = Ws[k][tx * TN + j];
#pragma unroll
            for (int i = 0; i < TM; i++)
#pragma unroll
                for (int j = 0; j < TN; j++) acc[i][j] += a[i] * b[j];
        }
        __syncthreads();
    }
#pragma unroll
    for (int i = 0; i < TM; i++) {
        int m = m0 + ty * TM + i;
#pragma unroll
        for (int j = 0; j < TN; j++) {
            int n = n0 + tx * TN + j;
            C[(size_t)m * NN + n] = acc[i][j] + bias[n];
        }
    }
}

// ---------------- x_s[b,n,o] = max_j lrelu(bn(t[(b,n,j),o])) -> cat ----------------
__global__ void maxk_kernel(const float* __restrict__ t, int O, int coff, int stage) {
    int i = blockIdx.x * 256 + threadIdx.x;            // over P*O
    int bn = i / O, c = i % O;
    float a = g_sc[stage][c], b = g_sh[stage][c];
    const float* base = t + (size_t)bn * KNN * O + c;
    float mx = NEG_INF;
#pragma unroll
    for (int j = 0; j < KNN; j++) {
        float v = a * base[(size_t)j * O] + b;
        v = v >= 0.f ? v : SLOPE * v;
        mx = fmaxf(mx, v);
    }
    g_cat[(size_t)bn * 512 + coff + c] = mx;
}

// ---------------- final: out[bn, o] = lrelu(bn6(t6)) ----------------
__global__ void final_kernel(float* __restrict__ out) {
    int i = blockIdx.x * 256 + threadIdx.x;            // over P*1024
    int c = i & 1023;
    float v = g_sc[5][c] * g_t6[i] + g_sh[5][c];
    out[i] = v >= 0.f ? v : SLOPE * v;
}

// ---------------- launch ----------------
static void run_stats(const float* t, int M, int O, float cnt, int stage,
                      const float* g, const float* be) {
    float *ps, *pq;
    cudaGetSymbolAddress((void**)&ps, g_ps);
    cudaGetSymbolAddress((void**)&pq, g_pq);
    int nb = M / 64;
    stats_partial<<<nb, 256>>>(t, O, ps, pq);
    stats_finalize<<<(O + 255) / 256, 256>>>(nb, O, cnt, stage, g, be);
}

extern "C" void kernel_launch(void* const* d_in, const int* in_sizes, int n_in,
                              void* d_out, int out_size) {
    const float* x  = (const float*)d_in[0];
    const float* w1 = (const float*)d_in[1];
    const float* b1 = (const float*)d_in[2];
    const float* g1 = (const float*)d_in[3];
    const float* be1= (const float*)d_in[4];
    const float* w2 = (const float*)d_in[5];
    const float* b2 = (const float*)d_in[6];
    const float* g2 = (const float*)d_in[7];
    const float* be2= (const float*)d_in[8];
    const float* w3 = (const float*)d_in[9];
    const float* b3 = (const float*)d_in[10];
    const float* g3 = (const float*)d_in[11];
    const float* be3= (const float*)d_in[12];
    const float* w4 = (const float*)d_in[13];
    const float* b4 = (const float*)d_in[14];
    const float* g4 = (const float*)d_in[15];
    const float* be4= (const float*)d_in[16];
    const float* w5 = (const float*)d_in[17];
    const float* b5 = (const float*)d_in[18];
    const float* g5 = (const float*)d_in[19];
    const float* be5= (const float*)d_in[20];
    const float* w6 = (const float*)d_in[21];
    const float* b6 = (const float*)d_in[22];
    const float* g6 = (const float*)d_in[23];
    const float* be6= (const float*)d_in[24];
    float* out = (float*)d_out;

    float *t1, *t2, *t3, *t4, *t5, *t6, *cat, *scb, *shb;
    cudaGetSymbolAddress((void**)&t1, g_t1);
    cudaGetSymbolAddress((void**)&t2, g_t2);
    cudaGetSymbolAddress((void**)&t3, g_t3);
    cudaGetSymbolAddress((void**)&t4, g_t4);
    cudaGetSymbolAddress((void**)&t5, g_t5);
    cudaGetSymbolAddress((void**)&t6, g_t6);
    cudaGetSymbolAddress((void**)&cat, g_cat);
    cudaGetSymbolAddress((void**)&scb, g_sc);
    cudaGetSymbolAddress((void**)&shb, g_sh);

    // KNN
    xx_kernel<<<P / 256, 256>>>(x);
    pd_kernel<<<dim3(16, 16, Bb), 256>>>(x);
    topk_kernel<<<P, 256>>>();

    // Stage 1: decomposed conv + gather
    qp_kernel<<<dim3(16, Bb), 256>>>(x, w1);
    s1_kernel<<<M4 / 4, 256>>>(b1);
    run_stats(t1, M4, 64, (float)M4, 0, g1, be1);

    // Stage 2: h1 -> t2   (BN1+lrelu folded into A-load)
    gemm_kernel<128, 64, 16, 8, 4, true>
        <<<dim3(1, M4 / 128), 256>>>(t1, w2, b2, scb + 0 * 1024, shb + 0 * 1024, t2, 64, 64);
    maxk_kernel<<<P * 64 / 256, 256>>>(t1, 64, 0, 0);          // x1
    run_stats(t2, M4, 64, (float)M4, 1, g2, be2);

    // Stage 3
    gemm_kernel<128, 128, 16, 8, 8, true>
        <<<dim3(1, M4 / 128), 256>>>(t2, w3, b3, scb + 1 * 1024, shb + 1 * 1024, t3, 64, 128);
    maxk_kernel<<<P * 64 / 256, 256>>>(t2, 64, 64, 1);         // x2
    run_stats(t3, M4, 128, (float)M4, 2, g3, be3);

    // Stage 4
    gemm_kernel<128, 128, 16, 8, 8, true>
        <<<dim3(2, M4 / 128), 256>>>(t3, w4, b4, scb + 2 * 1024, shb + 2 * 1024, t4, 128, 256);
    maxk_kernel<<<P * 128 / 256, 256>>>(t3, 128, 128, 2);      // x3
    run_stats(t4, M4, 256, (float)M4, 3, g4, be4);
    maxk_kernel<<<P * 256 / 256, 256>>>(t4, 256, 256, 3);      // x4

    // Stage 5: cat (already activated) -> t5
    gemm_kernel<128, 128, 16, 8, 8, false>
        <<<dim3(2, P / 128), 256>>>(cat, w5, b5, nullptr, nullptr, t5, 512, 256);
    run_stats(t5, P, 256, (float)P, 4, g5, be5);

    // Stage 6
    gemm_kernel<128, 128, 16, 8, 8, true>
        <<<dim3(8, P / 128), 256>>>(t5, w6, b6, scb + 4 * 1024, shb + 4 * 1024, t6, 256, 1024);
    run_stats(t6, P, 1024, (float)P, 5, g6, be6);

    // Final BN+lrelu straight into output (B, N, 1024)
    final_kernel<<<P * 1024 / 256, 256>>>(out);
}

// round 5
// speedup vs baseline: 1.5487x; 1.5487x over previous
#include <cuda_runtime.h>
#include <cstdint>
#include <math.h>

// ---------------- Problem constants ----------------
constexpr int Bb   = 8;
constexpr int Dd   = 60;
constexpr int NP   = 1024;
constexpr int KNN  = 20;
constexpr int P    = Bb * NP;        // 8192 points
constexpr int M4   = P * KNN;        // 163840 graph-feature rows
constexpr float EPSV  = 1e-5f;
constexpr float SLOPE = 0.2f;

#define NEG_INF (__int_as_float(0xff800000))

// ---------------- Device scratch ----------------
__device__ float g_xx[P];
__device__ float g_pd[(size_t)Bb * NP * NP];           // 32 MB
__device__ int   g_idx[M4];
__device__ float g_q[(size_t)P * 64];
__device__ float g_p[(size_t)P * 64];
__device__ float g_t1[(size_t)M4 * 64];
__device__ float g_t2[(size_t)M4 * 64];
__device__ float g_t3[(size_t)M4 * 128];
__device__ float g_t4[(size_t)M4 * 256];
__device__ float g_cat[(size_t)P * 512];
__device__ float g_t5[(size_t)P * 256];
__device__ float g_t6[(size_t)P * 1024];
__device__ float g_ps[1 << 20];
__device__ float g_pq[1 << 20];
__device__ float g_sc[6][1024];
__device__ float g_sh[6][1024];

// ---------------- xx[b,n] = sum_d x^2 ----------------
__global__ void xx_kernel(const float* __restrict__ x) {
    int i = blockIdx.x * 256 + threadIdx.x;
    int b = i >> 10, n = i & 1023;
    const float* xb = x + (size_t)b * Dd * NP + n;
    float s = 0.f;
#pragma unroll
    for (int d = 0; d < Dd; d++) { float v = xb[d * NP]; s += v * v; }
    g_xx[i] = s;
}

// ---------------- pd[b,n,m] = 2*dot - xx_n - xx_m ----------------
__global__ void pd_kernel(const float* __restrict__ x) {
    int b  = blockIdx.z;
    int n0 = blockIdx.y * 64;
    int m0 = blockIdx.x * 64;
    __shared__ float Xa[Dd][64];
    __shared__ float Xb[Dd][64];
    const float* xb = x + (size_t)b * Dd * NP;
    for (int l = threadIdx.x; l < Dd * 64; l += 256) {
        int d = l >> 6, mm = l & 63;
        Xa[d][mm] = xb[d * NP + n0 + mm];
        Xb[d][mm] = xb[d * NP + m0 + mm];
    }
    __syncthreads();
    int tx = threadIdx.x & 15, ty = threadIdx.x >> 4;
    float acc[4][4] = {};
#pragma unroll
    for (int d = 0; d < Dd; d++) {
        float a[4], c[4];
#pragma unroll
        for (int i = 0; i < 4; i++) a[i] = Xa[d][ty * 4 + i];
#pragma unroll
        for (int j = 0; j < 4; j++) c[j] = Xb[d][tx * 4 + j];
#pragma unroll
        for (int i = 0; i < 4; i++)
#pragma unroll
            for (int j = 0; j < 4; j++) acc[i][j] += a[i] * c[j];
    }
#pragma unroll
    for (int i = 0; i < 4; i++) {
        int n = n0 + ty * 4 + i;
        float xn = g_xx[b * NP + n];
#pragma unroll
        for (int j = 0; j < 4; j++) {
            int m = m0 + tx * 4 + j;
            g_pd[((size_t)b << 20) + (size_t)n * NP + m] =
                2.f * acc[i][j] - xn - g_xx[b * NP + m];
        }
    }
}

// ---------------- top-k (k=20) ----------------
__global__ void topk_kernel() {
    int bn = blockIdx.x;
    const float* row = g_pd + (size_t)bn * NP;
    int tid = threadIdx.x;
    float v[4]; int mi[4];
#pragma unroll
    for (int i = 0; i < 4; i++) { mi[i] = i * 256 + tid; v[i] = row[mi[i]]; }
    __shared__ float sv[256];
    __shared__ int   si[256];
    for (int it = 0; it < KNN; it++) {
        float bv = v[0]; int bi = mi[0];
#pragma unroll
        for (int i = 1; i < 4; i++)
            if (v[i] > bv || (v[i] == bv && mi[i] < bi)) { bv = v[i]; bi = mi[i]; }
        sv[tid] = bv; si[tid] = bi;
        __syncthreads();
        for (int st = 128; st > 0; st >>= 1) {
            if (tid < st) {
                if (sv[tid + st] > sv[tid] ||
                    (sv[tid + st] == sv[tid] && si[tid + st] < si[tid])) {
                    sv[tid] = sv[tid + st]; si[tid] = si[tid + st];
                }
            }
            __syncthreads();
        }
        int w = si[0];
        if (tid == 0) g_idx[bn * KNN + it] = w;
#pragma unroll
        for (int i = 0; i < 4; i++) if (mi[i] == w) v[i] = NEG_INF;
        __syncthreads();
    }
}

// ---------------- q = A@x, p = (B-A)@x ----------------
__global__ void qp_kernel(const float* __restrict__ x, const float* __restrict__ w1) {
    int b  = blockIdx.y;
    int m0 = blockIdx.x * 64;
    __shared__ float xs[Dd][64];
    __shared__ float ws[64][120];
    const float* xb = x + (size_t)b * Dd * NP;
    for (int l = threadIdx.x; l < Dd * 64; l += 256) {
        int d = l >> 6, m = l & 63;
        xs[d][m] = xb[d * NP + m0 + m];
    }
    for (int l = threadIdx.x; l < 64 * 120; l += 256) ws[l / 120][l % 120] = w1[l];
    __syncthreads();
    int tx = threadIdx.x & 15, ty = threadIdx.x >> 4;
    float qa[4][4] = {}, pa[4][4] = {};
#pragma unroll
    for (int d = 0; d < Dd; d++) {
        float wa[4], wb[4], xm[4];
#pragma unroll
        for (int i = 0; i < 4; i++) {
            wa[i] = ws[ty * 4 + i][d];
            wb[i] = ws[ty * 4 + i][60 + d] - wa[i];
        }
#pragma unroll
        for (int j = 0; j < 4; j++) xm[j] = xs[d][tx * 4 + j];
#pragma unroll
        for (int i = 0; i < 4; i++)
#pragma unroll
            for (int j = 0; j < 4; j++) {
                qa[i][j] += wa[i] * xm[j];
                pa[i][j] += wb[i] * xm[j];
            }
    }
#pragma unroll
    for (int i = 0; i < 4; i++)
#pragma unroll
        for (int j = 0; j < 4; j++) {
            int o = ty * 4 + i, m = m0 + tx * 4 + j;
            size_t base = ((size_t)b * NP + m) * 64 + o;
            g_q[base] = qa[i][j];
            g_p[base] = pa[i][j];
        }
}

// ---------------- t1 gather ----------------
__global__ void s1_kernel(const float* __restrict__ b1) {
    int row = blockIdx.x * 4 + (threadIdx.x >> 6);
    int c = threadIdx.x & 63;
    int b = row / (NP * KNN);
    int rem = row % (NP * KNN);
    int n = rem / KNN;
    int m = g_idx[row];
    float v = g_q[((size_t)b * NP + m) * 64 + c] +
              g_p[((size_t)b * NP + n) * 64 + c] + b1[c];
    g_t1[(size_t)row * 64 + c] = v;
}

// ---------------- stats partial (only for t1) ----------------
__global__ void stats_partial(const float* __restrict__ t, int O, float* __restrict__ ps,
                              float* __restrict__ pq) {
    int r0 = blockIdx.x * 64;
    int tid = threadIdx.x;
    int gsz = 256 / O;
    int c = tid % O;
    int slot = tid / O;
    float s = 0.f, q = 0.f;
    for (int r = r0 + slot; r < r0 + 64; r += gsz) {
        float v = t[(size_t)r * O + c];
        s += v; q += v * v;
    }
    __shared__ float ss[256], sq[256];
    ss[tid] = s; sq[tid] = q;
    __syncthreads();
    for (int st = 128; st >= O; st >>= 1) {
        if (tid < st) { ss[tid] += ss[tid + st]; sq[tid] += sq[tid + st]; }
        __syncthreads();
    }
    if (tid < O) {
        ps[(size_t)blockIdx.x * O + tid] = ss[tid];
        pq[(size_t)blockIdx.x * O + tid] = sq[tid];
    }
}

__global__ void stats_finalize(int nb, int O, float cnt, int stage,
                               const float* __restrict__ g, const float* __restrict__ be) {
    int c = blockIdx.x * blockDim.x + threadIdx.x;
    if (c >= O) return;
    double s = 0.0, q = 0.0;
    for (int i = 0; i < nb; i++) {
        s += g_ps[(size_t)i * O + c];
        q += g_pq[(size_t)i * O + c];
    }
    double m = s / cnt;
    double v = q / cnt - m * m;
    float a = g[c] * rsqrtf((float)v + EPSV);
    g_sc[stage][c] = a;
    g_sh[stage][c] = be[c] - (float)m * a;
}

// =====================================================================
// Double-buffered SIMT GEMM: C[M,NN-slice] = act(A)[M,K] . W[O,K]^T + bias
//  - warp tile 64m x 32n, lane grid 8m x 4n, thread 8x8 via 2x2 float4 frags
//  - conflict-free smem fragment loads
//  - BN-stats partials (sum, sumsq of C) fused into epilogue
//  - TRANS: fold previous layer's BN scale/shift + LeakyReLU into A load
// =====================================================================
template <int BM, int BN, bool TRANS>
__global__ __launch_bounds__(256, 2) void gemm2_kernel(
    const float* __restrict__ A, const float* __restrict__ W,
    const float* __restrict__ bias, const float* __restrict__ tsc,
    const float* __restrict__ tsh, float* __restrict__ C,
    float* __restrict__ ps, float* __restrict__ pq, int K, int NN) {
    constexpr int BK = 16;
    constexpr int WM = BM / 64;            // warps along m
    constexpr int WN = BN / 32;            // warps along n
    static_assert(WM * WN == 8, "8 warps");
    constexpr int ALD = BM * BK / (256 * 4);
    constexpr int WLD = BN * BK / (256 * 4);

    __shared__ float As[2][BK][BM + 4];
    __shared__ float Ws[2][BK][BN + 4];
    __shared__ float rs[WM][BN];
    __shared__ float rq[WM][BN];

    int tid  = threadIdx.x;
    int warp = tid >> 5, lane = tid & 31;
    int wm = warp % WM, wn = warp / WM;
    int lm = lane & 7,  ln = lane >> 3;
    int m0 = blockIdx.y * BM;
    int n0 = blockIdx.x * BN;

    int mb = wm * 64 + lm * 4;             // +{0..3}, +32
    int nb = wn * 32 + ln * 4;             // +{0..3}, +16

    float4 apre[ALD], wpre[WLD];
    int r_a[ALD], kq_a[ALD];
#pragma unroll
    for (int u = 0; u < ALD; u++) { int i = tid + 256 * u; r_a[u] = i >> 2; kq_a[u] = i & 3; }
    int r_w[WLD], kq_w[WLD];
#pragma unroll
    for (int u = 0; u < WLD; u++) { int i = tid + 256 * u; r_w[u] = i >> 2; kq_w[u] = i & 3; }

    int tiles = K / BK;
    float acc[8][8] = {};

    // prologue load tile 0
#pragma unroll
    for (int u = 0; u < ALD; u++)
        apre[u] = *(const float4*)(A + (size_t)(m0 + r_a[u]) * K + kq_a[u] * 4);
#pragma unroll
    for (int u = 0; u < WLD; u++)
        wpre[u] = *(const float4*)(W + (size_t)(n0 + r_w[u]) * K + kq_w[u] * 4);

    // store tile 0 to buf 0
    {
#pragma unroll
        for (int u = 0; u < ALD; u++) {
            float vals[4] = {apre[u].x, apre[u].y, apre[u].z, apre[u].w};
#pragma unroll
            for (int e = 0; e < 4; e++) {
                float v = vals[e];
                if (TRANS) {
                    int kk = kq_a[u] * 4 + e;
                    v = v * tsc[kk] + tsh[kk];
                    v = v >= 0.f ? v : SLOPE * v;
                }
                As[0][kq_a[u] * 4 + e][r_a[u]] = v;
            }
        }
#pragma unroll
        for (int u = 0; u < WLD; u++) {
            Ws[0][kq_w[u] * 4 + 0][r_w[u]] = wpre[u].x;
            Ws[0][kq_w[u] * 4 + 1][r_w[u]] = wpre[u].y;
            Ws[0][kq_w[u] * 4 + 2][r_w[u]] = wpre[u].z;
            Ws[0][kq_w[u] * 4 + 3][r_w[u]] = wpre[u].w;
        }
    }
    __syncthreads();

    for (int t = 0; t < tiles; t++) {
        int cur = t & 1, nxt = cur ^ 1;
        bool has_next = (t + 1) < tiles;
        if (has_next) {
            int k0 = (t + 1) * BK;
#pragma unroll
            for (int u = 0; u < ALD; u++)
                apre[u] = *(const float4*)(A + (size_t)(m0 + r_a[u]) * K + k0 + kq_a[u] * 4);
#pragma unroll
            for (int u = 0; u < WLD; u++)
                wpre[u] = *(const float4*)(W + (size_t)(n0 + r_w[u]) * K + k0 + kq_w[u] * 4);
        }
#pragma unroll
        for (int k = 0; k < BK; k++) {
            float a[8], b[8];
            *(float4*)(a)     = *(const float4*)&As[cur][k][mb];
            *(float4*)(a + 4) = *(const float4*)&As[cur][k][mb + 32];
            *(float4*)(b)     = *(const float4*)&Ws[cur][k][nb];
            *(float4*)(b + 4) = *(const float4*)&Ws[cur][k][nb + 16];
#pragma unroll
            for (int i = 0; i < 8; i++)
#pragma unroll
                for (int j = 0; j < 8; j++) acc[i][j] += a[i] * b[j];
        }
        if (has_next) {
            int k0 = (t + 1) * BK;
#pragma unroll
            for (int u = 0; u < ALD; u++) {
                float vals[4] = {apre[u].x, apre[u].y, apre[u].z, apre[u].w};
#pragma unroll
                for (int e = 0; e < 4; e++) {
                    float v = vals[e];
                    if (TRANS) {
                        int kk = k0 + kq_a[u] * 4 + e;
                        v = v * tsc[kk] + tsh[kk];
                        v = v >= 0.f ? v : SLOPE * v;
                    }
                    As[nxt][kq_a[u] * 4 + e][r_a[u]] = v;
                }
            }
#pragma unroll
            for (int u = 0; u < WLD; u++) {
                Ws[nxt][kq_w[u] * 4 + 0][r_w[u]] = wpre[u].x;
                Ws[nxt][kq_w[u] * 4 + 1][r_w[u]] = wpre[u].y;
                Ws[nxt][kq_w[u] * 4 + 2][r_w[u]] = wpre[u].z;
                Ws[nxt][kq_w[u] * 4 + 3][r_w[u]] = wpre[u].w;
            }
        }
        __syncthreads();
    }

    // ---- epilogue: bias, store C, fused per-channel partial stats ----
    float bia[8];
#pragma unroll
    for (int j = 0; j < 8; j++) {
        int n = n0 + nb + (j < 4 ? j : 12 + j);        // j>=4 -> nb+16+(j-4)
        bia[j] = bias[n];
    }
    float s_j[8] = {}, q_j[8] = {};
#pragma unroll
    for (int i = 0; i < 8; i++) {
        int m = m0 + mb + (i < 4 ? i : 28 + i);        // i>=4 -> mb+32+(i-4)
        float4 v0, v1;
        float vrow[8];
#pragma unroll
        for (int j = 0; j < 8; j++) {
            float v = acc[i][j] + bia[j];
            vrow[j] = v;
            s_j[j] += v;
            q_j[j] += v * v;
        }
        v0 = make_float4(vrow[0], vrow[1], vrow[2], vrow[3]);
        v1 = make_float4(vrow[4], vrow[5], vrow[6], vrow[7]);
        *(float4*)(C + (size_t)m * NN + n0 + nb)      = v0;
        *(float4*)(C + (size_t)m * NN + n0 + nb + 16) = v1;
    }
    // reduce over lm (8 lanes, consecutive within group of same ln)
#pragma unroll
    for (int off = 1; off < 8; off <<= 1) {
#pragma unroll
        for (int j = 0; j < 8; j++) {
            s_j[j] += __shfl_xor_sync(0xffffffffu, s_j[j], off);
            q_j[j] += __shfl_xor_sync(0xffffffffu, q_j[j], off);
        }
    }
    __syncthreads();   // done with As/Ws usage boundaries; also orders rs/rq writes
    if (lm == 0) {
#pragma unroll
        for (int j = 0; j < 8; j++) {
            int c = nb + (j < 4 ? j : 12 + j);
            rs[wm][c] = s_j[j];
            rq[wm][c] = q_j[j];
        }
    }
    __syncthreads();
    for (int c = tid; c < BN; c += 256) {
        float s = 0.f, q = 0.f;
#pragma unroll
        for (int w = 0; w < WM; w++) { s += rs[w][c]; q += rq[w][c]; }
        ps[(size_t)blockIdx.y * NN + n0 + c] = s;
        pq[(size_t)blockIdx.y * NN + n0 + c] = q;
    }
}

// ---------------- maxk ----------------
__global__ void maxk_kernel(const float* __restrict__ t, int O, int coff, int stage) {
    int i = blockIdx.x * 256 + threadIdx.x;
    int bn = i / O, c = i % O;
    float a = g_sc[stage][c], b = g_sh[stage][c];
    const float* base = t + (size_t)bn * KNN * O + c;
    float mx = NEG_INF;
#pragma unroll
    for (int j = 0; j < KNN; j++) {
        float v = a * base[(size_t)j * O] + b;
        v = v >= 0.f ? v : SLOPE * v;
        mx = fmaxf(mx, v);
    }
    g_cat[(size_t)bn * 512 + coff + c] = mx;
}

// ---------------- final ----------------
__global__ void final_kernel(float* __restrict__ out) {
    int i = blockIdx.x * 256 + threadIdx.x;
    int c = i & 1023;
    float v = g_sc[5][c] * g_t6[i] + g_sh[5][c];
    out[i] = v >= 0.f ? v : SLOPE * v;
}

// ---------------- launch ----------------
extern "C" void kernel_launch(void* const* d_in, const int* in_sizes, int n_in,
                              void* d_out, int out_size) {
    const float* x  = (const float*)d_in[0];
    const float* w1 = (const float*)d_in[1];
    const float* b1 = (const float*)d_in[2];
    const float* g1 = (const float*)d_in[3];
    const float* be1= (const float*)d_in[4];
    const float* w2 = (const float*)d_in[5];
    const float* b2 = (const float*)d_in[6];
    const float* g2 = (const float*)d_in[7];
    const float* be2= (const float*)d_in[8];
    const float* w3 = (const float*)d_in[9];
    const float* b3 = (const float*)d_in[10];
    const float* g3 = (const float*)d_in[11];
    const float* be3= (const float*)d_in[12];
    const float* w4 = (const float*)d_in[13];
    const float* b4 = (const float*)d_in[14];
    const float* g4 = (const float*)d_in[15];
    const float* be4= (const float*)d_in[16];
    const float* w5 = (const float*)d_in[17];
    const float* b5 = (const float*)d_in[18];
    const float* g5 = (const float*)d_in[19];
    const float* be5= (const float*)d_in[20];
    const float* w6 = (const float*)d_in[21];
    const float* b6 = (const float*)d_in[22];
    const float* g6 = (const float*)d_in[23];
    const float* be6= (const float*)d_in[24];
    float* out = (float*)d_out;

    float *t1, *t2, *t3, *t4, *t5, *t6, *cat, *scb, *shb, *ps, *pq;
    cudaGetSymbolAddress((void**)&t1, g_t1);
    cudaGetSymbolAddress((void**)&t2, g_t2);
    cudaGetSymbolAddress((void**)&t3, g_t3);
    cudaGetSymbolAddress((void**)&t4, g_t4);
    cudaGetSymbolAddress((void**)&t5, g_t5);
    cudaGetSymbolAddress((void**)&t6, g_t6);
    cudaGetSymbolAddress((void**)&cat, g_cat);
    cudaGetSymbolAddress((void**)&scb, g_sc);
    cudaGetSymbolAddress((void**)&shb, g_sh);
    cudaGetSymbolAddress((void**)&ps, g_ps);
    cudaGetSymbolAddress((void**)&pq, g_pq);

    // KNN
    xx_kernel<<<P / 256, 256>>>(x);
    pd_kernel<<<dim3(16, 16, Bb), 256>>>(x);
    topk_kernel<<<P, 256>>>();

    // Stage 1: decomposed conv + gather; stats on t1 via separate pass
    qp_kernel<<<dim3(16, Bb), 256>>>(x, w1);
    s1_kernel<<<M4 / 4, 256>>>(b1);
    stats_partial<<<M4 / 64, 256>>>(t1, 64, ps, pq);
    stats_finalize<<<1, 256>>>(M4 / 64, 64, (float)M4, 0, g1, be1);

    // Stage 2: t1 -> t2 (BN1+lrelu folded); stats fused
    gemm2_kernel<256, 64, true><<<dim3(1, M4 / 256), 256>>>(
        t1, w2, b2, scb + 0 * 1024, shb + 0 * 1024, t2, ps, pq, 64, 64);
    maxk_kernel<<<P * 64 / 256, 256>>>(t1, 64, 0, 0);          // x1
    stats_finalize<<<1, 256>>>(M4 / 256, 64, (float)M4, 1, g2, be2);

    // Stage 3
    gemm2_kernel<128, 128, true><<<dim3(1, M4 / 128), 256>>>(
        t2, w3, b3, scb + 1 * 1024, shb + 1 * 1024, t3, ps, pq, 64, 128);
    maxk_kernel<<<P * 64 / 256, 256>>>(t2, 64, 64, 1);         // x2
    stats_finalize<<<1, 256>>>(M4 / 128, 128, (float)M4, 2, g3, be3);

    // Stage 4
    gemm2_kernel<128, 128, true><<<dim3(2, M4 / 128), 256>>>(
        t3, w4, b4, scb + 2 * 1024, shb + 2 * 1024, t4, ps, pq, 128, 256);
    maxk_kernel<<<P * 128 / 256, 256>>>(t3, 128, 128, 2);      // x3
    stats_finalize<<<1, 256>>>(M4 / 128, 256, (float)M4, 3, g4, be4);
    maxk_kernel<<<P * 256 / 256, 256>>>(t4, 256, 256, 3);      // x4

    // Stage 5: cat (post-activation) -> t5
    gemm2_kernel<128, 128, false><<<dim3(2, P / 128), 256>>>(
        cat, w5, b5, nullptr, nullptr, t5, ps, pq, 512, 256);
    stats_finalize<<<1, 256>>>(P / 128, 256, (float)P, 4, g5, be5);

    // Stage 6
    gemm2_kernel<128, 128, true><<<dim3(8, P / 128), 256>>>(
        t5, w6, b6, scb + 4 * 1024, shb + 4 * 1024, t6, ps, pq, 256, 1024);
    stats_finalize<<<4, 256>>>(P / 128, 1024, (float)P, 5, g6, be6);

    // Final BN+lrelu -> output (B, N, 1024)
    final_kernel<<<P * 1024 / 256, 256>>>(out);
}

// round 6
// speedup vs baseline: 1.5863x; 1.0243x over previous
#include <cuda_runtime.h>
#include <cstdint>
#include <math.h>

// ---------------- Problem constants ----------------
constexpr int Bb   = 8;
constexpr int Dd   = 60;
constexpr int NP   = 1024;
constexpr int KNN  = 20;
constexpr int P    = Bb * NP;        // 8192 points
constexpr int M4   = P * KNN;        // 163840 graph-feature rows
constexpr float EPSV  = 1e-5f;
constexpr float SLOPE = 0.2f;

#define NEG_INF (__int_as_float(0xff800000))

// ---------------- packed f32x2 helpers ----------------
__device__ __forceinline__ unsigned long long pack2b(float v) {
    unsigned long long r;
    asm("mov.b64 %0, {%1, %1};" : "=l"(r) : "f"(v));
    return r;
}
__device__ __forceinline__ void ffma2(unsigned long long& d, unsigned long long a,
                                      unsigned long long b) {
    asm("fma.rn.f32x2 %0, %1, %2, %0;" : "+l"(d) : "l"(a), "l"(b));
}
__device__ __forceinline__ void unpack2(unsigned long long p, float& lo, float& hi) {
    asm("mov.b64 {%0, %1}, %2;" : "=f"(lo), "=f"(hi) : "l"(p));
}

// ---------------- Device scratch ----------------
__device__ float g_xx[P];
__device__ float g_pd[(size_t)Bb * NP * NP];           // 32 MB
__device__ int   g_idx[M4];
__device__ float g_q[(size_t)P * 64];
__device__ float g_p[(size_t)P * 64];
__device__ float g_t1[(size_t)M4 * 64];
__device__ float g_t2[(size_t)M4 * 64];
__device__ float g_t3[(size_t)M4 * 128];
__device__ float g_t4[(size_t)M4 * 256];
__device__ float g_cat[(size_t)P * 512];
__device__ float g_t5[(size_t)P * 256];
__device__ float g_t6[(size_t)P * 1024];
__device__ float g_ps[1 << 20];
__device__ float g_pq[1 << 20];
__device__ float g_sc[6][1024];
__device__ float g_sh[6][1024];

// ---------------- xx[b,n] = sum_d x^2 ----------------
__global__ void xx_kernel(const float* __restrict__ x) {
    int i = blockIdx.x * 256 + threadIdx.x;
    int b = i >> 10, n = i & 1023;
    const float* xb = x + (size_t)b * Dd * NP + n;
    float s = 0.f;
#pragma unroll
    for (int d = 0; d < Dd; d++) { float v = xb[d * NP]; s += v * v; }
    g_xx[i] = s;
}

// ---------------- pd[b,n,m] = 2*dot - xx_n - xx_m ----------------
__global__ void pd_kernel(const float* __restrict__ x) {
    int b  = blockIdx.z;
    int n0 = blockIdx.y * 64;
    int m0 = blockIdx.x * 64;
    __shared__ float Xa[Dd][64];
    __shared__ float Xb[Dd][64];
    const float* xb = x + (size_t)b * Dd * NP;
    for (int l = threadIdx.x; l < Dd * 64; l += 256) {
        int d = l >> 6, mm = l & 63;
        Xa[d][mm] = xb[d * NP + n0 + mm];
        Xb[d][mm] = xb[d * NP + m0 + mm];
    }
    __syncthreads();
    int tx = threadIdx.x & 15, ty = threadIdx.x >> 4;
    float acc[4][4] = {};
#pragma unroll
    for (int d = 0; d < Dd; d++) {
        float a[4], c[4];
#pragma unroll
        for (int i = 0; i < 4; i++) a[i] = Xa[d][ty * 4 + i];
#pragma unroll
        for (int j = 0; j < 4; j++) c[j] = Xb[d][tx * 4 + j];
#pragma unroll
        for (int i = 0; i < 4; i++)
#pragma unroll
            for (int j = 0; j < 4; j++) acc[i][j] += a[i] * c[j];
    }
#pragma unroll
    for (int i = 0; i < 4; i++) {
        int n = n0 + ty * 4 + i;
        float xn = g_xx[b * NP + n];
#pragma unroll
        for (int j = 0; j < 4; j++) {
            int m = m0 + tx * 4 + j;
            g_pd[((size_t)b << 20) + (size_t)n * NP + m] =
                2.f * acc[i][j] - xn - g_xx[b * NP + m];
        }
    }
}

// ---------------- top-k (k=20) ----------------
__global__ void topk_kernel() {
    int bn = blockIdx.x;
    const float* row = g_pd + (size_t)bn * NP;
    int tid = threadIdx.x;
    float v[4]; int mi[4];
#pragma unroll
    for (int i = 0; i < 4; i++) { mi[i] = i * 256 + tid; v[i] = row[mi[i]]; }
    __shared__ float sv[256];
    __shared__ int   si[256];
    for (int it = 0; it < KNN; it++) {
        float bv = v[0]; int bi = mi[0];
#pragma unroll
        for (int i = 1; i < 4; i++)
            if (v[i] > bv || (v[i] == bv && mi[i] < bi)) { bv = v[i]; bi = mi[i]; }
        sv[tid] = bv; si[tid] = bi;
        __syncthreads();
        for (int st = 128; st > 0; st >>= 1) {
            if (tid < st) {
                if (sv[tid + st] > sv[tid] ||
                    (sv[tid + st] == sv[tid] && si[tid + st] < si[tid])) {
                    sv[tid] = sv[tid + st]; si[tid] = si[tid + st];
                }
            }
            __syncthreads();
        }
        int w = si[0];
        if (tid == 0) g_idx[bn * KNN + it] = w;
#pragma unroll
        for (int i = 0; i < 4; i++) if (mi[i] == w) v[i] = NEG_INF;
        __syncthreads();
    }
}

// ---------------- q = A@x, p = (B-A)@x ----------------
__global__ void qp_kernel(const float* __restrict__ x, const float* __restrict__ w1) {
    int b  = blockIdx.y;
    int m0 = blockIdx.x * 64;
    __shared__ float xs[Dd][64];
    __shared__ float ws[64][120];
    const float* xb = x + (size_t)b * Dd * NP;
    for (int l = threadIdx.x; l < Dd * 64; l += 256) {
        int d = l >> 6, m = l & 63;
        xs[d][m] = xb[d * NP + m0 + m];
    }
    for (int l = threadIdx.x; l < 64 * 120; l += 256) ws[l / 120][l % 120] = w1[l];
    __syncthreads();
    int tx = threadIdx.x & 15, ty = threadIdx.x >> 4;
    float qa[4][4] = {}, pa[4][4] = {};
#pragma unroll
    for (int d = 0; d < Dd; d++) {
        float wa[4], wb[4], xm[4];
#pragma unroll
        for (int i = 0; i < 4; i++) {
            wa[i] = ws[ty * 4 + i][d];
            wb[i] = ws[ty * 4 + i][60 + d] - wa[i];
        }
#pragma unroll
        for (int j = 0; j < 4; j++) xm[j] = xs[d][tx * 4 + j];
#pragma unroll
        for (int i = 0; i < 4; i++)
#pragma unroll
            for (int j = 0; j < 4; j++) {
                qa[i][j] += wa[i] * xm[j];
                pa[i][j] += wb[i] * xm[j];
            }
    }
#pragma unroll
    for (int i = 0; i < 4; i++)
#pragma unroll
        for (int j = 0; j < 4; j++) {
            int o = ty * 4 + i, m = m0 + tx * 4 + j;
            size_t base = ((size_t)b * NP + m) * 64 + o;
            g_q[base] = qa[i][j];
            g_p[base] = pa[i][j];
        }
}

// ---------------- t1 gather ----------------
__global__ void s1_kernel(const float* __restrict__ b1) {
    int row = blockIdx.x * 4 + (threadIdx.x >> 6);
    int c = threadIdx.x & 63;
    int b = row / (NP * KNN);
    int rem = row % (NP * KNN);
    int n = rem / KNN;
    int m = g_idx[row];
    float v = g_q[((size_t)b * NP + m) * 64 + c] +
              g_p[((size_t)b * NP + n) * 64 + c] + b1[c];
    g_t1[(size_t)row * 64 + c] = v;
}

// ---------------- stats partial (only for t1) ----------------
__global__ void stats_partial(const float* __restrict__ t, int O, float* __restrict__ ps,
                              float* __restrict__ pq) {
    int r0 = blockIdx.x * 64;
    int tid = threadIdx.x;
    int gsz = 256 / O;
    int c = tid % O;
    int slot = tid / O;
    float s = 0.f, q = 0.f;
    for (int r = r0 + slot; r < r0 + 64; r += gsz) {
        float v = t[(size_t)r * O + c];
        s += v; q += v * v;
    }
    __shared__ float ss[256], sq[256];
    ss[tid] = s; sq[tid] = q;
    __syncthreads();
    for (int st = 128; st >= O; st >>= 1) {
        if (tid < st) { ss[tid] += ss[tid + st]; sq[tid] += sq[tid + st]; }
        __syncthreads();
    }
    if (tid < O) {
        ps[(size_t)blockIdx.x * O + tid] = ss[tid];
        pq[(size_t)blockIdx.x * O + tid] = sq[tid];
    }
}

__global__ void stats_finalize(int nb, int O, float cnt, int stage,
                               const float* __restrict__ g, const float* __restrict__ be) {
    int c = blockIdx.x * blockDim.x + threadIdx.x;
    if (c >= O) return;
    double s = 0.0, q = 0.0;
    for (int i = 0; i < nb; i++) {
        s += g_ps[(size_t)i * O + c];
        q += g_pq[(size_t)i * O + c];
    }
    double m = s / cnt;
    double v = q / cnt - m * m;
    float a = g[c] * rsqrtf((float)v + EPSV);
    g_sc[stage][c] = a;
    g_sh[stage][c] = be[c] - (float)m * a;
}

// =====================================================================
// Double-buffered FFMA2 GEMM: C = act(A)[M,K] . W[O,K]^T + bias
//  - inner loop uses packed fma.rn.f32x2 (2 fp32 FMA / issue slot)
//  - acc: 8(m) x 4 packed (n,n+1) pairs per thread
//  - fused per-channel partial BN stats in epilogue
// =====================================================================
template <int BM, int BN, bool TRANS>
__global__ __launch_bounds__(256, 2) void gemm2_kernel(
    const float* __restrict__ A, const float* __restrict__ W,
    const float* __restrict__ bias, const float* __restrict__ tsc,
    const float* __restrict__ tsh, float* __restrict__ C,
    float* __restrict__ ps, float* __restrict__ pq, int K, int NN) {
    constexpr int BK = 16;
    constexpr int WM = BM / 64;
    constexpr int WN = BN / 32;
    static_assert(WM * WN == 8, "8 warps");
    constexpr int ALD = BM * BK / (256 * 4);
    constexpr int WLD = BN * BK / (256 * 4);

    __shared__ float As[2][BK][BM + 4];
    __shared__ float Ws[2][BK][BN + 4];
    __shared__ float rs[WM][BN];
    __shared__ float rq[WM][BN];

    int tid  = threadIdx.x;
    int warp = tid >> 5, lane = tid & 31;
    int wm = warp % WM, wn = warp / WM;
    int lm = lane & 7,  ln = lane >> 3;
    int m0 = blockIdx.y * BM;
    int n0 = blockIdx.x * BN;

    int mb = wm * 64 + lm * 4;
    int nb = wn * 32 + ln * 4;

    float4 apre[ALD], wpre[WLD];
    int r_a[ALD], kq_a[ALD];
#pragma unroll
    for (int u = 0; u < ALD; u++) { int i = tid + 256 * u; r_a[u] = i >> 2; kq_a[u] = i & 3; }
    int r_w[WLD], kq_w[WLD];
#pragma unroll
    for (int u = 0; u < WLD; u++) { int i = tid + 256 * u; r_w[u] = i >> 2; kq_w[u] = i & 3; }

    int tiles = K / BK;
    unsigned long long accp[8][4];
#pragma unroll
    for (int i = 0; i < 8; i++)
#pragma unroll
        for (int jp = 0; jp < 4; jp++) accp[i][jp] = 0ull;

    // prologue: load + store tile 0
#pragma unroll
    for (int u = 0; u < ALD; u++)
        apre[u] = *(const float4*)(A + (size_t)(m0 + r_a[u]) * K + kq_a[u] * 4);
#pragma unroll
    for (int u = 0; u < WLD; u++)
        wpre[u] = *(const float4*)(W + (size_t)(n0 + r_w[u]) * K + kq_w[u] * 4);
    {
#pragma unroll
        for (int u = 0; u < ALD; u++) {
            float vals[4] = {apre[u].x, apre[u].y, apre[u].z, apre[u].w};
#pragma unroll
            for (int e = 0; e < 4; e++) {
                float v = vals[e];
                if (TRANS) {
                    int kk = kq_a[u] * 4 + e;
                    v = v * tsc[kk] + tsh[kk];
                    v = v >= 0.f ? v : SLOPE * v;
                }
                As[0][kq_a[u] * 4 + e][r_a[u]] = v;
            }
        }
#pragma unroll
        for (int u = 0; u < WLD; u++) {
            Ws[0][kq_w[u] * 4 + 0][r_w[u]] = wpre[u].x;
            Ws[0][kq_w[u] * 4 + 1][r_w[u]] = wpre[u].y;
            Ws[0][kq_w[u] * 4 + 2][r_w[u]] = wpre[u].z;
            Ws[0][kq_w[u] * 4 + 3][r_w[u]] = wpre[u].w;
        }
    }
    __syncthreads();

    for (int t = 0; t < tiles; t++) {
        int cur = t & 1, nxt = cur ^ 1;
        bool has_next = (t + 1) < tiles;
        if (has_next) {
            int k0 = (t + 1) * BK;
#pragma unroll
            for (int u = 0; u < ALD; u++)
                apre[u] = *(const float4*)(A + (size_t)(m0 + r_a[u]) * K + k0 + kq_a[u] * 4);
#pragma unroll
            for (int u = 0; u < WLD; u++)
                wpre[u] = *(const float4*)(W + (size_t)(n0 + r_w[u]) * K + k0 + kq_w[u] * 4);
        }
#pragma unroll
        for (int k = 0; k < BK; k++) {
            float4 a0 = *(const float4*)&As[cur][k][mb];
            float4 a1 = *(const float4*)&As[cur][k][mb + 32];
            ulonglong2 b0 = *(const ulonglong2*)&Ws[cur][k][nb];
            ulonglong2 b1 = *(const ulonglong2*)&Ws[cur][k][nb + 16];
            unsigned long long bp[4] = {b0.x, b0.y, b1.x, b1.y};
            float av[8] = {a0.x, a0.y, a0.z, a0.w, a1.x, a1.y, a1.z, a1.w};
#pragma unroll
            for (int i = 0; i < 8; i++) {
                unsigned long long ap = pack2b(av[i]);
#pragma unroll
                for (int jp = 0; jp < 4; jp++) ffma2(accp[i][jp], ap, bp[jp]);
            }
        }
        if (has_next) {
            int k0 = (t + 1) * BK;
#pragma unroll
            for (int u = 0; u < ALD; u++) {
                float vals[4] = {apre[u].x, apre[u].y, apre[u].z, apre[u].w};
#pragma unroll
                for (int e = 0; e < 4; e++) {
                    float v = vals[e];
                    if (TRANS) {
                        int kk = k0 + kq_a[u] * 4 + e;
                        v = v * tsc[kk] + tsh[kk];
                        v = v >= 0.f ? v : SLOPE * v;
                    }
                    As[nxt][kq_a[u] * 4 + e][r_a[u]] = v;
                }
            }
#pragma unroll
            for (int u = 0; u < WLD; u++) {
                Ws[nxt][kq_w[u] * 4 + 0][r_w[u]] = wpre[u].x;
                Ws[nxt][kq_w[u] * 4 + 1][r_w[u]] = wpre[u].y;
                Ws[nxt][kq_w[u] * 4 + 2][r_w[u]] = wpre[u].z;
                Ws[nxt][kq_w[u] * 4 + 3][r_w[u]] = wpre[u].w;
            }
        }
        __syncthreads();
    }

    // ---- epilogue: bias, store C, fused per-channel partial stats ----
    float bia[8];
#pragma unroll
    for (int j = 0; j < 8; j++) {
        int n = n0 + nb + (j < 4 ? j : 12 + j);
        bia[j] = bias[n];
    }
    float s_j[8] = {}, q_j[8] = {};
#pragma unroll
    for (int i = 0; i < 8; i++) {
        int m = m0 + mb + (i < 4 ? i : 28 + i);
        float vrow[8];
        unpack2(accp[i][0], vrow[0], vrow[1]);
        unpack2(accp[i][1], vrow[2], vrow[3]);
        unpack2(accp[i][2], vrow[4], vrow[5]);
        unpack2(accp[i][3], vrow[6], vrow[7]);
#pragma unroll
        for (int j = 0; j < 8; j++) {
            float v = vrow[j] + bia[j];
            vrow[j] = v;
            s_j[j] += v;
            q_j[j] += v * v;
        }
        *(float4*)(C + (size_t)m * NN + n0 + nb) =
            make_float4(vrow[0], vrow[1], vrow[2], vrow[3]);
        *(float4*)(C + (size_t)m * NN + n0 + nb + 16) =
            make_float4(vrow[4], vrow[5], vrow[6], vrow[7]);
    }
#pragma unroll
    for (int off = 1; off < 8; off <<= 1) {
#pragma unroll
        for (int j = 0; j < 8; j++) {
            s_j[j] += __shfl_xor_sync(0xffffffffu, s_j[j], off);
            q_j[j] += __shfl_xor_sync(0xffffffffu, q_j[j], off);
        }
    }
    __syncthreads();
    if (lm == 0) {
#pragma unroll
        for (int j = 0; j < 8; j++) {
            int c = nb + (j < 4 ? j : 12 + j);
            rs[wm][c] = s_j[j];
            rq[wm][c] = q_j[j];
        }
    }
    __syncthreads();
    for (int c = tid; c < BN; c += 256) {
        float s = 0.f, q = 0.f;
#pragma unroll
        for (int w = 0; w < WM; w++) { s += rs[w][c]; q += rq[w][c]; }
        ps[(size_t)blockIdx.y * NN + n0 + c] = s;
        pq[(size_t)blockIdx.y * NN + n0 + c] = q;
    }
}

// ---------------- maxk ----------------
__global__ void maxk_kernel(const float* __restrict__ t, int O, int coff, int stage) {
    int i = blockIdx.x * 256 + threadIdx.x;
    int bn = i / O, c = i % O;
    float a = g_sc[stage][c], b = g_sh[stage][c];
    const float* base = t + (size_t)bn * KNN * O + c;
    float mx = NEG_INF;
#pragma unroll
    for (int j = 0; j < KNN; j++) {
        float v = a * base[(size_t)j * O] + b;
        v = v >= 0.f ? v : SLOPE * v;
        mx = fmaxf(mx, v);
    }
    g_cat[(size_t)bn * 512 + coff + c] = mx;
}

// ---------------- final ----------------
__global__ void final_kernel(float* __restrict__ out) {
    int i = blockIdx.x * 256 + threadIdx.x;
    int c = i & 1023;
    float v = g_sc[5][c] * g_t6[i] + g_sh[5][c];
    out[i] = v >= 0.f ? v : SLOPE * v;
}

// ---------------- launch ----------------
extern "C" void kernel_launch(void* const* d_in, const int* in_sizes, int n_in,
                              void* d_out, int out_size) {
    const float* x  = (const float*)d_in[0];
    const float* w1 = (const float*)d_in[1];
    const float* b1 = (const float*)d_in[2];
    const float* g1 = (const float*)d_in[3];
    const float* be1= (const float*)d_in[4];
    const float* w2 = (const float*)d_in[5];
    const float* b2 = (const float*)d_in[6];
    const float* g2 = (const float*)d_in[7];
    const float* be2= (const float*)d_in[8];
    const float* w3 = (const float*)d_in[9];
    const float* b3 = (const float*)d_in[10];
    const float* g3 = (const float*)d_in[11];
    const float* be3= (const float*)d_in[12];
    const float* w4 = (const float*)d_in[13];
    const float* b4 = (const float*)d_in[14];
    const float* g4 = (const float*)d_in[15];
    const float* be4= (const float*)d_in[16];
    const float* w5 = (const float*)d_in[17];
    const float* b5 = (const float*)d_in[18];
    const float* g5 = (const float*)d_in[19];
    const float* be5= (const float*)d_in[20];
    const float* w6 = (const float*)d_in[21];
    const float* b6 = (const float*)d_in[22];
    const float* g6 = (const float*)d_in[23];
    const float* be6= (const float*)d_in[24];
    float* out = (float*)d_out;

    float *t1, *t2, *t3, *t4, *t5, *t6, *cat, *scb, *shb, *ps, *pq;
    cudaGetSymbolAddress((void**)&t1, g_t1);
    cudaGetSymbolAddress((void**)&t2, g_t2);
    cudaGetSymbolAddress((void**)&t3, g_t3);
    cudaGetSymbolAddress((void**)&t4, g_t4);
    cudaGetSymbolAddress((void**)&t5, g_t5);
    cudaGetSymbolAddress((void**)&t6, g_t6);
    cudaGetSymbolAddress((void**)&cat, g_cat);
    cudaGetSymbolAddress((void**)&scb, g_sc);
    cudaGetSymbolAddress((void**)&shb, g_sh);
    cudaGetSymbolAddress((void**)&ps, g_ps);
    cudaGetSymbolAddress((void**)&pq, g_pq);

    // KNN
    xx_kernel<<<P / 256, 256>>>(x);
    pd_kernel<<<dim3(16, 16, Bb), 256>>>(x);
    topk_kernel<<<P, 256>>>();

    // Stage 1: decomposed conv + gather; stats on t1 via separate pass
    qp_kernel<<<dim3(16, Bb), 256>>>(x, w1);
    s1_kernel<<<M4 / 4, 256>>>(b1);
    stats_partial<<<M4 / 64, 256>>>(t1, 64, ps, pq);
    stats_finalize<<<1, 256>>>(M4 / 64, 64, (float)M4, 0, g1, be1);

    // Stage 2: t1 -> t2 (BN1+lrelu folded); stats fused
    gemm2_kernel<256, 64, true><<<dim3(1, M4 / 256), 256>>>(
        t1, w2, b2, scb + 0 * 1024, shb + 0 * 1024, t2, ps, pq, 64, 64);
    maxk_kernel<<<P * 64 / 256, 256>>>(t1, 64, 0, 0);          // x1
    stats_finalize<<<1, 256>>>(M4 / 256, 64, (float)M4, 1, g2, be2);

    // Stage 3
    gemm2_kernel<128, 128, true><<<dim3(1, M4 / 128), 256>>>(
        t2, w3, b3, scb + 1 * 1024, shb + 1 * 1024, t3, ps, pq, 64, 128);
    maxk_kernel<<<P * 64 / 256, 256>>>(t2, 64, 64, 1);         // x2
    stats_finalize<<<1, 256>>>(M4 / 128, 128, (float)M4, 2, g3, be3);

    // Stage 4
    gemm2_kernel<128, 128, true><<<dim3(2, M4 / 128), 256>>>(
        t3, w4, b4, scb + 2 * 1024, shb + 2 * 1024, t4, ps, pq, 128, 256);
    maxk_kernel<<<P * 128 / 256, 256>>>(t3, 128, 128, 2);      // x3
    stats_finalize<<<1, 256>>>(M4 / 128, 256, (float)M4, 3, g4, be4);
    maxk_kernel<<<P * 256 / 256, 256>>>(t4, 256, 256, 3);      // x4

    // Stage 5: cat (post-activation) -> t5
    gemm2_kernel<128, 128, false><<<dim3(2, P / 128), 256>>>(
        cat, w5, b5, nullptr, nullptr, t5, ps, pq, 512, 256);
    stats_finalize<<<1, 256>>>(P / 128, 256, (float)P, 4, g5, be5);

    // Stage 6
    gemm2_kernel<128, 128, true><<<dim3(8, P / 128), 256>>>(
        t5, w6, b6, scb + 4 * 1024, shb + 4 * 1024, t6, ps, pq, 256, 1024);
    stats_finalize<<<4, 256>>>(P / 128, 1024, (float)P, 5, g6, be6);

    // Final BN+lrelu -> output (B, N, 1024)
    final_kernel<<<P * 1024 / 256, 256>>>(out);
}

// round 7
// speedup vs baseline: 1.9373x; 1.2212x over previous
#include <cuda_runtime.h>
#include <cstdint>
#include <math.h>

// ---------------- Problem constants ----------------
constexpr int Bb   = 8;
constexpr int Dd   = 60;
constexpr int NP   = 1024;
constexpr int KNN  = 20;
constexpr int P    = Bb * NP;        // 8192 points
constexpr int M4   = P * KNN;        // 163840 graph-feature rows
constexpr float EPSV  = 1e-5f;
constexpr float SLOPE = 0.2f;

#define NEG_INF (__int_as_float(0xff800000))

// ---------------- packed f32x2 helpers ----------------
__device__ __forceinline__ unsigned long long pack2b(float v) {
    unsigned long long r;
    asm("mov.b64 %0, {%1, %1};" : "=l"(r) : "f"(v));
    return r;
}
__device__ __forceinline__ void ffma2(unsigned long long& d, unsigned long long a,
                                      unsigned long long b) {
    asm("fma.rn.f32x2 %0, %1, %2, %0;" : "+l"(d) : "l"(a), "l"(b));
}
__device__ __forceinline__ void unpack2(unsigned long long p, float& lo, float& hi) {
    asm("mov.b64 {%0, %1}, %2;" : "=f"(lo), "=f"(hi) : "l"(p));
}
// exact float max via atomics (order-independent => deterministic)
__device__ __forceinline__ void amax_f(float* a, float v) {
    if (v >= 0.f) atomicMax((int*)a, __float_as_int(v));
    else          atomicMin((unsigned int*)a, __float_as_uint(v));
}

// ---------------- Device scratch ----------------
__device__ float g_xx[P];
__device__ float g_pd[(size_t)Bb * NP * NP];           // 32 MB
__device__ int   g_idx[M4];
__device__ float g_q[(size_t)P * 64];
__device__ float g_p[(size_t)P * 64];
__device__ float g_t1[(size_t)M4 * 64];
__device__ float g_t2[(size_t)M4 * 64];
__device__ float g_t3[(size_t)M4 * 128];
__device__ float g_cat[(size_t)P * 512];               // RAW per-point maxes
__device__ float g_t5[(size_t)P * 256];
__device__ float g_t6[(size_t)P * 1024];
__device__ float g_ps[1 << 20];
__device__ float g_pq[1 << 20];
__device__ float g_sc[6][1024];
__device__ float g_sh[6][1024];
__device__ float g_csc[512];                           // concat sc/sh for cat channels
__device__ float g_csh[512];

// ---------------- init cat to -inf ----------------
__global__ void init_cat(float* __restrict__ cat) {
    cat[blockIdx.x * 256 + threadIdx.x] = NEG_INF;
}

// ---------------- xx[b,n] = sum_d x^2 ----------------
__global__ void xx_kernel(const float* __restrict__ x) {
    int i = blockIdx.x * 256 + threadIdx.x;
    int b = i >> 10, n = i & 1023;
    const float* xb = x + (size_t)b * Dd * NP + n;
    float s = 0.f;
#pragma unroll
    for (int d = 0; d < Dd; d++) { float v = xb[d * NP]; s += v * v; }
    g_xx[i] = s;
}

// ---------------- pd[b,n,m] = 2*dot - xx_n - xx_m ----------------
__global__ void pd_kernel(const float* __restrict__ x) {
    int b  = blockIdx.z;
    int n0 = blockIdx.y * 64;
    int m0 = blockIdx.x * 64;
    __shared__ float Xa[Dd][64];
    __shared__ float Xb[Dd][64];
    const float* xb = x + (size_t)b * Dd * NP;
    for (int l = threadIdx.x; l < Dd * 64; l += 256) {
        int d = l >> 6, mm = l & 63;
        Xa[d][mm] = xb[d * NP + n0 + mm];
        Xb[d][mm] = xb[d * NP + m0 + mm];
    }
    __syncthreads();
    int tx = threadIdx.x & 15, ty = threadIdx.x >> 4;
    float acc[4][4] = {};
#pragma unroll
    for (int d = 0; d < Dd; d++) {
        float a[4], c[4];
#pragma unroll
        for (int i = 0; i < 4; i++) a[i] = Xa[d][ty * 4 + i];
#pragma unroll
        for (int j = 0; j < 4; j++) c[j] = Xb[d][tx * 4 + j];
#pragma unroll
        for (int i = 0; i < 4; i++)
#pragma unroll
            for (int j = 0; j < 4; j++) acc[i][j] += a[i] * c[j];
    }
#pragma unroll
    for (int i = 0; i < 4; i++) {
        int n = n0 + ty * 4 + i;
        float xn = g_xx[b * NP + n];
#pragma unroll
        for (int j = 0; j < 4; j++) {
            int m = m0 + tx * 4 + j;
            g_pd[((size_t)b << 20) + (size_t)n * NP + m] =
                2.f * acc[i][j] - xn - g_xx[b * NP + m];
        }
    }
}

// ---------------- top-k (k=20) ----------------
__global__ void topk_kernel() {
    int bn = blockIdx.x;
    const float* row = g_pd + (size_t)bn * NP;
    int tid = threadIdx.x;
    float v[4]; int mi[4];
#pragma unroll
    for (int i = 0; i < 4; i++) { mi[i] = i * 256 + tid; v[i] = row[mi[i]]; }
    __shared__ float sv[256];
    __shared__ int   si[256];
    for (int it = 0; it < KNN; it++) {
        float bv = v[0]; int bi = mi[0];
#pragma unroll
        for (int i = 1; i < 4; i++)
            if (v[i] > bv || (v[i] == bv && mi[i] < bi)) { bv = v[i]; bi = mi[i]; }
        sv[tid] = bv; si[tid] = bi;
        __syncthreads();
        for (int st = 128; st > 0; st >>= 1) {
            if (tid < st) {
                if (sv[tid + st] > sv[tid] ||
                    (sv[tid + st] == sv[tid] && si[tid + st] < si[tid])) {
                    sv[tid] = sv[tid + st]; si[tid] = si[tid + st];
                }
            }
            __syncthreads();
        }
        int w = si[0];
        if (tid == 0) g_idx[bn * KNN + it] = w;
#pragma unroll
        for (int i = 0; i < 4; i++) if (mi[i] == w) v[i] = NEG_INF;
        __syncthreads();
    }
}

// ---------------- q = A@x, p = (B-A)@x ----------------
__global__ void qp_kernel(const float* __restrict__ x, const float* __restrict__ w1) {
    int b  = blockIdx.y;
    int m0 = blockIdx.x * 64;
    __shared__ float xs[Dd][64];
    __shared__ float ws[64][120];
    const float* xb = x + (size_t)b * Dd * NP;
    for (int l = threadIdx.x; l < Dd * 64; l += 256) {
        int d = l >> 6, m = l & 63;
        xs[d][m] = xb[d * NP + m0 + m];
    }
    for (int l = threadIdx.x; l < 64 * 120; l += 256) ws[l / 120][l % 120] = w1[l];
    __syncthreads();
    int tx = threadIdx.x & 15, ty = threadIdx.x >> 4;
    float qa[4][4] = {}, pa[4][4] = {};
#pragma unroll
    for (int d = 0; d < Dd; d++) {
        float wa[4], wb[4], xm[4];
#pragma unroll
        for (int i = 0; i < 4; i++) {
            wa[i] = ws[ty * 4 + i][d];
            wb[i] = ws[ty * 4 + i][60 + d] - wa[i];
        }
#pragma unroll
        for (int j = 0; j < 4; j++) xm[j] = xs[d][tx * 4 + j];
#pragma unroll
        for (int i = 0; i < 4; i++)
#pragma unroll
            for (int j = 0; j < 4; j++) {
                qa[i][j] += wa[i] * xm[j];
                pa[i][j] += wb[i] * xm[j];
            }
    }
#pragma unroll
    for (int i = 0; i < 4; i++)
#pragma unroll
        for (int j = 0; j < 4; j++) {
            int o = ty * 4 + i, m = m0 + tx * 4 + j;
            size_t base = ((size_t)b * NP + m) * 64 + o;
            g_q[base] = qa[i][j];
            g_p[base] = pa[i][j];
        }
}

// ---------------- s1: gather -> t1, fused per-channel stats + x1 raw max ----------------
// one block per point: 20 rows x 64 channels; slot js covers j = js, js+4, ...
__global__ __launch_bounds__(256) void s1_kernel(const float* __restrict__ b1,
                                                 float* __restrict__ ps,
                                                 float* __restrict__ pq,
                                                 float* __restrict__ cat) {
    int bn = blockIdx.x;                               // 0..8191
    int tid = threadIdx.x;
    int c = tid & 63, js = tid >> 6;
    int b = bn >> 10;
    float pv = g_p[(size_t)bn * 64 + c] + b1[c];
    int rbase = bn * KNN;
    float mx = NEG_INF, s = 0.f, q = 0.f;
#pragma unroll
    for (int jj = 0; jj < 5; jj++) {
        int row = rbase + js + jj * 4;
        int m = g_idx[row];
        float v = g_q[((size_t)(b << 10) + m) * 64 + c] + pv;
        g_t1[(size_t)row * 64 + c] = v;
        mx = fmaxf(mx, v); s += v; q += v * v;
    }
    __shared__ float smx[4][64], ssm[4][64], sqm[4][64];
    smx[js][c] = mx; ssm[js][c] = s; sqm[js][c] = q;
    __syncthreads();
    if (js == 0) {
        float M = smx[0][c], S = ssm[0][c], Q = sqm[0][c];
#pragma unroll
        for (int k = 1; k < 4; k++) {
            M = fmaxf(M, smx[k][c]); S += ssm[k][c]; Q += sqm[k][c];
        }
        cat[(size_t)bn * 512 + c] = M;                 // raw max, x1 slot
        ps[(size_t)bn * 64 + c] = S;
        pq[(size_t)bn * 64 + c] = Q;
    }
}

// ---------------- parallel stats finalize ----------------
// grid = O/64 blocks, 256 threads: 4 slots x 64 channels
__global__ void stats_finalize(const float* __restrict__ ps, const float* __restrict__ pq,
                               int nb, int O, float cnt, int stage, int coff,
                               const float* __restrict__ g, const float* __restrict__ be) {
    int c = blockIdx.x * 64 + (threadIdx.x & 63);
    int slot = threadIdx.x >> 6;
    double s = 0.0, q = 0.0;
    for (int i = slot; i < nb; i += 4) {
        s += ps[(size_t)i * O + c];
        q += pq[(size_t)i * O + c];
    }
    __shared__ double ds[4][64], dq[4][64];
    ds[slot][threadIdx.x & 63] = s;
    dq[slot][threadIdx.x & 63] = q;
    __syncthreads();
    if (slot == 0) {
        int t = threadIdx.x & 63;
        double S = ds[0][t], Q = dq[0][t];
#pragma unroll
        for (int k = 1; k < 4; k++) { S += ds[k][t]; Q += dq[k][t]; }
        double m = S / cnt;
        double v = Q / cnt - m * m;
        float a  = g[c] * rsqrtf((float)v + EPSV);
        float sh = be[c] - (float)m * a;
        g_sc[stage][c] = a;
        g_sh[stage][c] = sh;
        if (coff >= 0) { g_csc[coff + c] = a; g_csh[coff + c] = sh; }
    }
}

// =====================================================================
// Double-buffered FFMA2 GEMM with fused stats + optional fused raw max
//   C = act(A)[M,K] . W[O,K]^T + bias
//   MAXF: per-point (row/20) raw max merged into cat via exact atomics
//   WRITE_C=false: output tensor never materialized (stage 4)
// =====================================================================
template <int BM, int BN, bool TRANS, bool WRITE_C, bool MAXF>
__global__ __launch_bounds__(256, 2) void gemm2_kernel(
    const float* __restrict__ A, const float* __restrict__ W,
    const float* __restrict__ bias, const float* __restrict__ tsc,
    const float* __restrict__ tsh, float* __restrict__ C,
    float* __restrict__ ps, float* __restrict__ pq, int K, int NN,
    float* __restrict__ cat, int coff) {
    constexpr int BK = 16;
    constexpr int WM = BM / 64;
    constexpr int WN = BN / 32;
    static_assert(WM * WN == 8, "8 warps");
    constexpr int ALD = BM * BK / (256 * 4);
    constexpr int WLD = BN * BK / (256 * 4);
    constexpr int PTS = BM / 20 + 2;

    __shared__ float As[2][BK][BM + 4];
    __shared__ float Ws[2][BK][BN + 4];
    __shared__ float rs[WM][BN];
    __shared__ float rq[WM][BN];
    __shared__ float smax[MAXF ? PTS : 1][MAXF ? BN : 1];

    int tid  = threadIdx.x;
    int warp = tid >> 5, lane = tid & 31;
    int wm = warp % WM, wn = warp / WM;
    int lm = lane & 7,  ln = lane >> 3;
    int m0 = blockIdx.y * BM;
    int n0 = blockIdx.x * BN;
    int p_base = m0 / KNN;

    if (MAXF) {
        for (int i = tid; i < PTS * BN; i += 256)
            ((float*)smax)[i] = NEG_INF;
    }

    int mb = wm * 64 + lm * 4;
    int nb = wn * 32 + ln * 4;

    float4 apre[ALD], wpre[WLD];
    int r_a[ALD], kq_a[ALD];
#pragma unroll
    for (int u = 0; u < ALD; u++) { int i = tid + 256 * u; r_a[u] = i >> 2; kq_a[u] = i & 3; }
    int r_w[WLD], kq_w[WLD];
#pragma unroll
    for (int u = 0; u < WLD; u++) { int i = tid + 256 * u; r_w[u] = i >> 2; kq_w[u] = i & 3; }

    int tiles = K / BK;
    unsigned long long accp[8][4];
#pragma unroll
    for (int i = 0; i < 8; i++)
#pragma unroll
        for (int jp = 0; jp < 4; jp++) accp[i][jp] = 0ull;

    // prologue: load + store tile 0
#pragma unroll
    for (int u = 0; u < ALD; u++)
        apre[u] = *(const float4*)(A + (size_t)(m0 + r_a[u]) * K + kq_a[u] * 4);
#pragma unroll
    for (int u = 0; u < WLD; u++)
        wpre[u] = *(const float4*)(W + (size_t)(n0 + r_w[u]) * K + kq_w[u] * 4);
    {
#pragma unroll
        for (int u = 0; u < ALD; u++) {
            float vals[4] = {apre[u].x, apre[u].y, apre[u].z, apre[u].w};
#pragma unroll
            for (int e = 0; e < 4; e++) {
                float v = vals[e];
                if (TRANS) {
                    int kk = kq_a[u] * 4 + e;
                    v = v * tsc[kk] + tsh[kk];
                    v = v >= 0.f ? v : SLOPE * v;
                }
                As[0][kq_a[u] * 4 + e][r_a[u]] = v;
            }
        }
#pragma unroll
        for (int u = 0; u < WLD; u++) {
            Ws[0][kq_w[u] * 4 + 0][r_w[u]] = wpre[u].x;
            Ws[0][kq_w[u] * 4 + 1][r_w[u]] = wpre[u].y;
            Ws[0][kq_w[u] * 4 + 2][r_w[u]] = wpre[u].z;
            Ws[0][kq_w[u] * 4 + 3][r_w[u]] = wpre[u].w;
        }
    }
    __syncthreads();

    for (int t = 0; t < tiles; t++) {
        int cur = t & 1, nxt = cur ^ 1;
        bool has_next = (t + 1) < tiles;
        if (has_next) {
            int k0 = (t + 1) * BK;
#pragma unroll
            for (int u = 0; u < ALD; u++)
                apre[u] = *(const float4*)(A + (size_t)(m0 + r_a[u]) * K + k0 + kq_a[u] * 4);
#pragma unroll
            for (int u = 0; u < WLD; u++)
                wpre[u] = *(const float4*)(W + (size_t)(n0 + r_w[u]) * K + k0 + kq_w[u] * 4);
        }
#pragma unroll
        for (int k = 0; k < BK; k++) {
            float4 a0 = *(const float4*)&As[cur][k][mb];
            float4 a1 = *(const float4*)&As[cur][k][mb + 32];
            ulonglong2 b0 = *(const ulonglong2*)&Ws[cur][k][nb];
            ulonglong2 b1 = *(const ulonglong2*)&Ws[cur][k][nb + 16];
            unsigned long long bp[4] = {b0.x, b0.y, b1.x, b1.y};
            float av[8] = {a0.x, a0.y, a0.z, a0.w, a1.x, a1.y, a1.z, a1.w};
#pragma unroll
            for (int i = 0; i < 8; i++) {
                unsigned long long ap = pack2b(av[i]);
#pragma unroll
                for (int jp = 0; jp < 4; jp++) ffma2(accp[i][jp], ap, bp[jp]);
            }
        }
        if (has_next) {
            int k0 = (t + 1) * BK;
#pragma unroll
            for (int u = 0; u < ALD; u++) {
                float vals[4] = {apre[u].x, apre[u].y, apre[u].z, apre[u].w};
#pragma unroll
                for (int e = 0; e < 4; e++) {
                    float v = vals[e];
                    if (TRANS) {
                        int kk = k0 + kq_a[u] * 4 + e;
                        v = v * tsc[kk] + tsh[kk];
                        v = v >= 0.f ? v : SLOPE * v;
                    }
                    As[nxt][kq_a[u] * 4 + e][r_a[u]] = v;
                }
            }
#pragma unroll
            for (int u = 0; u < WLD; u++) {
                Ws[nxt][kq_w[u] * 4 + 0][r_w[u]] = wpre[u].x;
                Ws[nxt][kq_w[u] * 4 + 1][r_w[u]] = wpre[u].y;
                Ws[nxt][kq_w[u] * 4 + 2][r_w[u]] = wpre[u].z;
                Ws[nxt][kq_w[u] * 4 + 3][r_w[u]] = wpre[u].w;
            }
        }
        __syncthreads();
    }

    // ---- epilogue: bias, (store C), fused stats, (fused raw max) ----
    float bia[8];
#pragma unroll
    for (int j = 0; j < 8; j++) {
        int n = n0 + nb + (j < 4 ? j : 12 + j);
        bia[j] = bias[n];
    }
    float s_j[8] = {}, q_j[8] = {};
#pragma unroll
    for (int i = 0; i < 8; i++) {
        int mrow = mb + (i < 4 ? i : 28 + i);
        int m = m0 + mrow;
        float vrow[8];
        unpack2(accp[i][0], vrow[0], vrow[1]);
        unpack2(accp[i][1], vrow[2], vrow[3]);
        unpack2(accp[i][2], vrow[4], vrow[5]);
        unpack2(accp[i][3], vrow[6], vrow[7]);
#pragma unroll
        for (int j = 0; j < 8; j++) {
            float v = vrow[j] + bia[j];
            vrow[j] = v;
            s_j[j] += v;
            q_j[j] += v * v;
        }
        if (WRITE_C) {
            *(float4*)(C + (size_t)m * NN + n0 + nb) =
                make_float4(vrow[0], vrow[1], vrow[2], vrow[3]);
            *(float4*)(C + (size_t)m * NN + n0 + nb + 16) =
                make_float4(vrow[4], vrow[5], vrow[6], vrow[7]);
        }
        if (MAXF) {
            int pl = m / KNN - p_base;
#pragma unroll
            for (int j = 0; j < 8; j++) {
                int c = nb + (j < 4 ? j : 12 + j);
                amax_f(&smax[pl][c], vrow[j]);
            }
        }
    }
#pragma unroll
    for (int off = 1; off < 8; off <<= 1) {
#pragma unroll
        for (int j = 0; j < 8; j++) {
            s_j[j] += __shfl_xor_sync(0xffffffffu, s_j[j], off);
            q_j[j] += __shfl_xor_sync(0xffffffffu, q_j[j], off);
        }
    }
    __syncthreads();
    if (lm == 0) {
#pragma unroll
        for (int j = 0; j < 8; j++) {
            int c = nb + (j < 4 ? j : 12 + j);
            rs[wm][c] = s_j[j];
            rq[wm][c] = q_j[j];
        }
    }
    __syncthreads();
    for (int c = tid; c < BN; c += 256) {
        float s = 0.f, q = 0.f;
#pragma unroll
        for (int w = 0; w < WM; w++) { s += rs[w][c]; q += rq[w][c]; }
        ps[(size_t)blockIdx.y * NN + n0 + c] = s;
        pq[(size_t)blockIdx.y * NN + n0 + c] = q;
    }
    if (MAXF) {
        int npts = (m0 + BM - 1) / KNN - p_base + 1;
        for (int idx = tid; idx < npts * BN; idx += 256) {
            int pl = idx / BN, c = idx % BN;
            float v = smax[pl][c];
            if (v > NEG_INF)
                amax_f(&cat[(size_t)(p_base + pl) * 512 + coff + n0 + c], v);
        }
    }
}

// ---------------- final ----------------
__global__ void final_kernel(float* __restrict__ out) {
    int i = blockIdx.x * 256 + threadIdx.x;
    int c = i & 1023;
    float v = g_sc[5][c] * g_t6[i] + g_sh[5][c];
    out[i] = v >= 0.f ? v : SLOPE * v;
}

// ---------------- launch ----------------
extern "C" void kernel_launch(void* const* d_in, const int* in_sizes, int n_in,
                              void* d_out, int out_size) {
    const float* x  = (const float*)d_in[0];
    const float* w1 = (const float*)d_in[1];
    const float* b1 = (const float*)d_in[2];
    const float* g1 = (const float*)d_in[3];
    const float* be1= (const float*)d_in[4];
    const float* w2 = (const float*)d_in[5];
    const float* b2 = (const float*)d_in[6];
    const float* g2 = (const float*)d_in[7];
    const float* be2= (const float*)d_in[8];
    const float* w3 = (const float*)d_in[9];
    const float* b3 = (const float*)d_in[10];
    const float* g3 = (const float*)d_in[11];
    const float* be3= (const float*)d_in[12];
    const float* w4 = (const float*)d_in[13];
    const float* b4 = (const float*)d_in[14];
    const float* g4 = (const float*)d_in[15];
    const float* be4= (const float*)d_in[16];
    const float* w5 = (const float*)d_in[17];
    const float* b5 = (const float*)d_in[18];
    const float* g5 = (const float*)d_in[19];
    const float* be5= (const float*)d_in[20];
    const float* w6 = (const float*)d_in[21];
    const float* b6 = (const float*)d_in[22];
    const float* g6 = (const float*)d_in[23];
    const float* be6= (const float*)d_in[24];
    float* out = (float*)d_out;

    float *t1, *t2, *t3, *t5, *t6, *cat, *scb, *shb, *csc, *csh, *ps, *pq;
    cudaGetSymbolAddress((void**)&t1, g_t1);
    cudaGetSymbolAddress((void**)&t2, g_t2);
    cudaGetSymbolAddress((void**)&t3, g_t3);
    cudaGetSymbolAddress((void**)&t5, g_t5);
    cudaGetSymbolAddress((void**)&t6, g_t6);
    cudaGetSymbolAddress((void**)&cat, g_cat);
    cudaGetSymbolAddress((void**)&scb, g_sc);
    cudaGetSymbolAddress((void**)&shb, g_sh);
    cudaGetSymbolAddress((void**)&csc, g_csc);
    cudaGetSymbolAddress((void**)&csh, g_csh);
    cudaGetSymbolAddress((void**)&ps, g_ps);
    cudaGetSymbolAddress((void**)&pq, g_pq);

    // init cat to -inf (atomic-max accumulator)
    init_cat<<<P * 512 / 256, 256>>>(cat);

    // KNN
    xx_kernel<<<P / 256, 256>>>(x);
    pd_kernel<<<dim3(16, 16, Bb), 256>>>(x);
    topk_kernel<<<P, 256>>>();

    // Stage 1: decomposed conv + gather; fused stats + x1 raw max
    qp_kernel<<<dim3(16, Bb), 256>>>(x, w1);
    s1_kernel<<<P, 256>>>(b1, ps, pq, cat);
    stats_finalize<<<1, 256>>>(ps, pq, P, 64, (float)M4, 0, 0, g1, be1);

    // Stage 2: t1 -> t2 (BN1+lrelu folded); fused stats + x2 raw max
    gemm2_kernel<256, 64, true, true, true><<<dim3(1, M4 / 256), 256>>>(
        t1, w2, b2, scb + 0 * 1024, shb + 0 * 1024, t2, ps, pq, 64, 64, cat, 64);
    stats_finalize<<<1, 256>>>(ps, pq, M4 / 256, 64, (float)M4, 1, 64, g2, be2);

    // Stage 3: fused stats + x3 raw max
    gemm2_kernel<128, 128, true, true, true><<<dim3(1, M4 / 128), 256>>>(
        t2, w3, b3, scb + 1 * 1024, shb + 1 * 1024, t3, ps, pq, 64, 128, cat, 128);
    stats_finalize<<<2, 256>>>(ps, pq, M4 / 128, 128, (float)M4, 2, 128, g3, be3);

    // Stage 4: no C write at all; fused stats + x4 raw max
    gemm2_kernel<128, 128, true, false, true><<<dim3(2, M4 / 128), 256>>>(
        t3, w4, b4, scb + 2 * 1024, shb + 2 * 1024, nullptr, ps, pq, 128, 256, cat, 256);
    stats_finalize<<<4, 256>>>(ps, pq, M4 / 128, 256, (float)M4, 3, 256, g4, be4);

    // Stage 5: raw cat -> t5, folding all four stages' BN+lrelu via csc/csh
    gemm2_kernel<128, 128, true, true, false><<<dim3(2, P / 128), 256>>>(
        cat, w5, b5, csc, csh, t5, ps, pq, 512, 256, nullptr, 0);
    stats_finalize<<<4, 256>>>(ps, pq, P / 128, 256, (float)P, 4, -1, g5, be5);

    // Stage 6
    gemm2_kernel<128, 128, true, true, false><<<dim3(8, P / 128), 256>>>(
        t5, w6, b6, scb + 4 * 1024, shb + 4 * 1024, t6, ps, pq, 256, 1024, nullptr, 0);
    stats_finalize<<<16, 256>>>(ps, pq, P / 128, 1024, (float)P, 5, -1, g6, be6);

    // Final BN+lrelu -> output (B, N, 1024)
    final_kernel<<<P * 1024 / 256, 256>>>(out);
}

// round 8
// speedup vs baseline: 2.0739x; 1.0705x over previous
#include <cuda_runtime.h>
#include <cstdint>
#include <math.h>

// ---------------- Problem constants ----------------
constexpr int Bb   = 8;
constexpr int Dd   = 60;
constexpr int NP   = 1024;
constexpr int KNN  = 20;
constexpr int P    = Bb * NP;        // 8192 points
constexpr int M4   = P * KNN;        // 163840 graph-feature rows
constexpr float EPSV  = 1e-5f;
constexpr float SLOPE = 0.2f;

#define NEG_INF (__int_as_float(0xff800000))

// ---------------- packed f32x2 helpers ----------------
__device__ __forceinline__ unsigned long long pack2b(float v) {
    unsigned long long r;
    asm("mov.b64 %0, {%1, %1};" : "=l"(r) : "f"(v));
    return r;
}
__device__ __forceinline__ void ffma2(unsigned long long& d, unsigned long long a,
                                      unsigned long long b) {
    asm("fma.rn.f32x2 %0, %1, %2, %0;" : "+l"(d) : "l"(a), "l"(b));
}
__device__ __forceinline__ void unpack2(unsigned long long p, float& lo, float& hi) {
    asm("mov.b64 {%0, %1}, %2;" : "=f"(lo), "=f"(hi) : "l"(p));
}
// exact float max via atomics (order-independent => deterministic)
__device__ __forceinline__ void amax_f(float* a, float v) {
    if (v >= 0.f) atomicMax((int*)a, __float_as_int(v));
    else          atomicMin((unsigned int*)a, __float_as_uint(v));
}

// ---------------- Device scratch ----------------
__device__ float g_xx[P];
__device__ float g_pd[(size_t)Bb * NP * NP];           // 32 MB
__device__ int   g_idx[M4];
__device__ float g_q[(size_t)P * 64];
__device__ float g_p[(size_t)P * 64];
__device__ float g_t1[(size_t)M4 * 64];
__device__ float g_t2[(size_t)M4 * 64];
__device__ float g_t3[(size_t)M4 * 128];
__device__ float g_cat[(size_t)P * 512];               // RAW per-point maxes
__device__ float g_t5[(size_t)P * 256];
__device__ float g_t6[(size_t)P * 1024];
__device__ float g_ps[1 << 20];
__device__ float g_pq[1 << 20];
__device__ float g_sc[6][1024];
__device__ float g_sh[6][1024];
__device__ float g_csc[512];                           // concat sc/sh for cat channels
__device__ float g_csh[512];

// ---------------- init cat to -inf ----------------
__global__ void init_cat(float* __restrict__ cat) {
    cat[blockIdx.x * 256 + threadIdx.x] = NEG_INF;
}

// ---------------- xx[b,n] = sum_d x^2 ----------------
__global__ void xx_kernel(const float* __restrict__ x) {
    int i = blockIdx.x * 256 + threadIdx.x;
    int b = i >> 10, n = i & 1023;
    const float* xb = x + (size_t)b * Dd * NP + n;
    float s = 0.f;
#pragma unroll
    for (int d = 0; d < Dd; d++) { float v = xb[d * NP]; s += v * v; }
    g_xx[i] = s;
}

// ---------------- pd[b,n,m] = 2*dot - xx_n - xx_m ----------------
__global__ void pd_kernel(const float* __restrict__ x) {
    int b  = blockIdx.z;
    int n0 = blockIdx.y * 64;
    int m0 = blockIdx.x * 64;
    __shared__ float Xa[Dd][64];
    __shared__ float Xb[Dd][64];
    const float* xb = x + (size_t)b * Dd * NP;
    for (int l = threadIdx.x; l < Dd * 64; l += 256) {
        int d = l >> 6, mm = l & 63;
        Xa[d][mm] = xb[d * NP + n0 + mm];
        Xb[d][mm] = xb[d * NP + m0 + mm];
    }
    __syncthreads();
    int tx = threadIdx.x & 15, ty = threadIdx.x >> 4;
    float acc[4][4] = {};
#pragma unroll
    for (int d = 0; d < Dd; d++) {
        float a[4], c[4];
#pragma unroll
        for (int i = 0; i < 4; i++) a[i] = Xa[d][ty * 4 + i];
#pragma unroll
        for (int j = 0; j < 4; j++) c[j] = Xb[d][tx * 4 + j];
#pragma unroll
        for (int i = 0; i < 4; i++)
#pragma unroll
            for (int j = 0; j < 4; j++) acc[i][j] += a[i] * c[j];
    }
#pragma unroll
    for (int i = 0; i < 4; i++) {
        int n = n0 + ty * 4 + i;
        float xn = g_xx[b * NP + n];
#pragma unroll
        for (int j = 0; j < 4; j++) {
            int m = m0 + tx * 4 + j;
            g_pd[((size_t)b << 20) + (size_t)n * NP + m] =
                2.f * acc[i][j] - xn - g_xx[b * NP + m];
        }
    }
}

// ---------------- warp-per-row top-k (k=20), barrier-free ----------------
// 16 warps/block, one row (1024 values) per warp; lane holds 32 values.
__global__ __launch_bounds__(512) void topk_kernel() {
    int warp = threadIdx.x >> 5, lane = threadIdx.x & 31;
    int bn = blockIdx.x * 16 + warp;                   // 0..8191
    const float* row = g_pd + (size_t)bn * NP;
    float v[32];
#pragma unroll
    for (int j = 0; j < 32; j++) v[j] = row[j * 32 + lane];
    // local argmax (ascending j + strict > => smallest slot on ties)
    float bv = v[0]; int bs = 0;
#pragma unroll
    for (int j = 1; j < 32; j++)
        if (v[j] > bv) { bv = v[j]; bs = j; }
    int* out = g_idx + bn * KNN;
    for (int it = 0; it < KNN; it++) {
        float rv = bv;
        int   ri = bs * 32 + lane;                     // global index in row
#pragma unroll
        for (int off = 16; off > 0; off >>= 1) {
            float ov = __shfl_xor_sync(0xffffffffu, rv, off);
            int   oi = __shfl_xor_sync(0xffffffffu, ri, off);
            if (ov > rv || (ov == rv && oi < ri)) { rv = ov; ri = oi; }
        }
        if (lane == 0) out[it] = ri;
        if ((ri & 31) == lane) {                       // winner lane: mask + recompute
            v[ri >> 5] = NEG_INF;
            bv = v[0]; bs = 0;
#pragma unroll
            for (int j = 1; j < 32; j++)
                if (v[j] > bv) { bv = v[j]; bs = j; }
        }
    }
}

// ---------------- q = A@x, p = (B-A)@x ----------------
__global__ void qp_kernel(const float* __restrict__ x, const float* __restrict__ w1) {
    int b  = blockIdx.y;
    int m0 = blockIdx.x * 64;
    __shared__ float xs[Dd][64];
    __shared__ float ws[64][120];
    const float* xb = x + (size_t)b * Dd * NP;
    for (int l = threadIdx.x; l < Dd * 64; l += 256) {
        int d = l >> 6, m = l & 63;
        xs[d][m] = xb[d * NP + m0 + m];
    }
    for (int l = threadIdx.x; l < 64 * 120; l += 256) ws[l / 120][l % 120] = w1[l];
    __syncthreads();
    int tx = threadIdx.x & 15, ty = threadIdx.x >> 4;
    float qa[4][4] = {}, pa[4][4] = {};
#pragma unroll
    for (int d = 0; d < Dd; d++) {
        float wa[4], wb[4], xm[4];
#pragma unroll
        for (int i = 0; i < 4; i++) {
            wa[i] = ws[ty * 4 + i][d];
            wb[i] = ws[ty * 4 + i][60 + d] - wa[i];
        }
#pragma unroll
        for (int j = 0; j < 4; j++) xm[j] = xs[d][tx * 4 + j];
#pragma unroll
        for (int i = 0; i < 4; i++)
#pragma unroll
            for (int j = 0; j < 4; j++) {
                qa[i][j] += wa[i] * xm[j];
                pa[i][j] += wb[i] * xm[j];
            }
    }
#pragma unroll
    for (int i = 0; i < 4; i++)
#pragma unroll
        for (int j = 0; j < 4; j++) {
            int o = ty * 4 + i, m = m0 + tx * 4 + j;
            size_t base = ((size_t)b * NP + m) * 64 + o;
            g_q[base] = qa[i][j];
            g_p[base] = pa[i][j];
        }
}

// ---------------- s1: gather -> t1, fused per-channel stats + x1 raw max ----------------
__global__ __launch_bounds__(256) void s1_kernel(const float* __restrict__ b1,
                                                 float* __restrict__ ps,
                                                 float* __restrict__ pq,
                                                 float* __restrict__ cat) {
    int bn = blockIdx.x;                               // 0..8191
    int tid = threadIdx.x;
    int c = tid & 63, js = tid >> 6;
    int b = bn >> 10;
    float pv = g_p[(size_t)bn * 64 + c] + b1[c];
    int rbase = bn * KNN;
    float mx = NEG_INF, s = 0.f, q = 0.f;
#pragma unroll
    for (int jj = 0; jj < 5; jj++) {
        int row = rbase + js + jj * 4;
        int m = g_idx[row];
        float v = g_q[((size_t)(b << 10) + m) * 64 + c] + pv;
        g_t1[(size_t)row * 64 + c] = v;
        mx = fmaxf(mx, v); s += v; q += v * v;
    }
    __shared__ float smx[4][64], ssm[4][64], sqm[4][64];
    smx[js][c] = mx; ssm[js][c] = s; sqm[js][c] = q;
    __syncthreads();
    if (js == 0) {
        float M = smx[0][c], S = ssm[0][c], Q = sqm[0][c];
#pragma unroll
        for (int k = 1; k < 4; k++) {
            M = fmaxf(M, smx[k][c]); S += ssm[k][c]; Q += sqm[k][c];
        }
        cat[(size_t)bn * 512 + c] = M;
        ps[(size_t)bn * 64 + c] = S;
        pq[(size_t)bn * 64 + c] = Q;
    }
}

// ---------------- parallel stats finalize ----------------
__global__ void stats_finalize(const float* __restrict__ ps, const float* __restrict__ pq,
                               int nb, int O, float cnt, int stage, int coff,
                               const float* __restrict__ g, const float* __restrict__ be) {
    int c = blockIdx.x * 64 + (threadIdx.x & 63);
    int slot = threadIdx.x >> 6;
    double s = 0.0, q = 0.0;
    for (int i = slot; i < nb; i += 4) {
        s += ps[(size_t)i * O + c];
        q += pq[(size_t)i * O + c];
    }
    __shared__ double ds[4][64], dq[4][64];
    ds[slot][threadIdx.x & 63] = s;
    dq[slot][threadIdx.x & 63] = q;
    __syncthreads();
    if (slot == 0) {
        int t = threadIdx.x & 63;
        double S = ds[0][t], Q = dq[0][t];
#pragma unroll
        for (int k = 1; k < 4; k++) { S += ds[k][t]; Q += dq[k][t]; }
        double m = S / cnt;
        double v = Q / cnt - m * m;
        float a  = g[c] * rsqrtf((float)v + EPSV);
        float sh = be[c] - (float)m * a;
        g_sc[stage][c] = a;
        g_sh[stage][c] = sh;
        if (coff >= 0) { g_csc[coff + c] = a; g_csh[coff + c] = sh; }
    }
}

// =====================================================================
// Double-buffered FFMA2 GEMM with fused stats + optional fused raw max
// =====================================================================
template <int BM, int BN, bool TRANS, bool WRITE_C, bool MAXF>
__global__ __launch_bounds__(256, 2) void gemm2_kernel(
    const float* __restrict__ A, const float* __restrict__ W,
    const float* __restrict__ bias, const float* __restrict__ tsc,
    const float* __restrict__ tsh, float* __restrict__ C,
    float* __restrict__ ps, float* __restrict__ pq, int K, int NN,
    float* __restrict__ cat, int coff) {
    constexpr int BK = 16;
    constexpr int WM = BM / 64;
    constexpr int WN = BN / 32;
    static_assert(WM * WN == 8, "8 warps");
    constexpr int ALD = BM * BK / (256 * 4);
    constexpr int WLD = BN * BK / (256 * 4);
    constexpr int PTS = BM / 20 + 2;

    __shared__ float As[2][BK][BM + 4];
    __shared__ float Ws[2][BK][BN + 4];
    __shared__ float rs[WM][BN];
    __shared__ float rq[WM][BN];
    __shared__ float smax[MAXF ? PTS : 1][MAXF ? BN : 1];

    int tid  = threadIdx.x;
    int warp = tid >> 5, lane = tid & 31;
    int wm = warp % WM, wn = warp / WM;
    int lm = lane & 7,  ln = lane >> 3;
    int m0 = blockIdx.y * BM;
    int n0 = blockIdx.x * BN;
    int p_base = m0 / KNN;

    if (MAXF) {
        for (int i = tid; i < PTS * BN; i += 256)
            ((float*)smax)[i] = NEG_INF;
    }

    int mb = wm * 64 + lm * 4;
    int nb = wn * 32 + ln * 4;

    float4 apre[ALD], wpre[WLD];
    int r_a[ALD], kq_a[ALD];
#pragma unroll
    for (int u = 0; u < ALD; u++) { int i = tid + 256 * u; r_a[u] = i >> 2; kq_a[u] = i & 3; }
    int r_w[WLD], kq_w[WLD];
#pragma unroll
    for (int u = 0; u < WLD; u++) { int i = tid + 256 * u; r_w[u] = i >> 2; kq_w[u] = i & 3; }

    int tiles = K / BK;
    unsigned long long accp[8][4];
#pragma unroll
    for (int i = 0; i < 8; i++)
#pragma unroll
        for (int jp = 0; jp < 4; jp++) accp[i][jp] = 0ull;

    // prologue: load + store tile 0
#pragma unroll
    for (int u = 0; u < ALD; u++)
        apre[u] = *(const float4*)(A + (size_t)(m0 + r_a[u]) * K + kq_a[u] * 4);
#pragma unroll
    for (int u = 0; u < WLD; u++)
        wpre[u] = *(const float4*)(W + (size_t)(n0 + r_w[u]) * K + kq_w[u] * 4);
    {
#pragma unroll
        for (int u = 0; u < ALD; u++) {
            float vals[4] = {apre[u].x, apre[u].y, apre[u].z, apre[u].w};
#pragma unroll
            for (int e = 0; e < 4; e++) {
                float v = vals[e];
                if (TRANS) {
                    int kk = kq_a[u] * 4 + e;
                    v = v * tsc[kk] + tsh[kk];
                    v = v >= 0.f ? v : SLOPE * v;
                }
                As[0][kq_a[u] * 4 + e][r_a[u]] = v;
            }
        }
#pragma unroll
        for (int u = 0; u < WLD; u++) {
            Ws[0][kq_w[u] * 4 + 0][r_w[u]] = wpre[u].x;
            Ws[0][kq_w[u] * 4 + 1][r_w[u]] = wpre[u].y;
            Ws[0][kq_w[u] * 4 + 2][r_w[u]] = wpre[u].z;
            Ws[0][kq_w[u] * 4 + 3][r_w[u]] = wpre[u].w;
        }
    }
    __syncthreads();

    for (int t = 0; t < tiles; t++) {
        int cur = t & 1, nxt = cur ^ 1;
        bool has_next = (t + 1) < tiles;
        if (has_next) {
            int k0 = (t + 1) * BK;
#pragma unroll
            for (int u = 0; u < ALD; u++)
                apre[u] = *(const float4*)(A + (size_t)(m0 + r_a[u]) * K + k0 + kq_a[u] * 4);
#pragma unroll
            for (int u = 0; u < WLD; u++)
                wpre[u] = *(const float4*)(W + (size_t)(n0 + r_w[u]) * K + k0 + kq_w[u] * 4);
        }
#pragma unroll
        for (int k = 0; k < BK; k++) {
            float4 a0 = *(const float4*)&As[cur][k][mb];
            float4 a1 = *(const float4*)&As[cur][k][mb + 32];
            ulonglong2 b0 = *(const ulonglong2*)&Ws[cur][k][nb];
            ulonglong2 b1 = *(const ulonglong2*)&Ws[cur][k][nb + 16];
            unsigned long long bp[4] = {b0.x, b0.y, b1.x, b1.y};
            float av[8] = {a0.x, a0.y, a0.z, a0.w, a1.x, a1.y, a1.z, a1.w};
#pragma unroll
            for (int i = 0; i < 8; i++) {
                unsigned long long ap = pack2b(av[i]);
#pragma unroll
                for (int jp = 0; jp < 4; jp++) ffma2(accp[i][jp], ap, bp[jp]);
            }
        }
        if (has_next) {
            int k0 = (t + 1) * BK;
#pragma unroll
            for (int u = 0; u < ALD; u++) {
                float vals[4] = {apre[u].x, apre[u].y, apre[u].z, apre[u].w};
#pragma unroll
                for (int e = 0; e < 4; e++) {
                    float v = vals[e];
                    if (TRANS) {
                        int kk = k0 + kq_a[u] * 4 + e;
                        v = v * tsc[kk] + tsh[kk];
                        v = v >= 0.f ? v : SLOPE * v;
                    }
                    As[nxt][kq_a[u] * 4 + e][r_a[u]] = v;
                }
            }
#pragma unroll
            for (int u = 0; u < WLD; u++) {
                Ws[nxt][kq_w[u] * 4 + 0][r_w[u]] = wpre[u].x;
                Ws[nxt][kq_w[u] * 4 + 1][r_w[u]] = wpre[u].y;
                Ws[nxt][kq_w[u] * 4 + 2][r_w[u]] = wpre[u].z;
                Ws[nxt][kq_w[u] * 4 + 3][r_w[u]] = wpre[u].w;
            }
        }
        __syncthreads();
    }

    // ---- epilogue: bias, (store C), fused stats, (fused raw max) ----
    float bia[8];
#pragma unroll
    for (int j = 0; j < 8; j++) {
        int n = n0 + nb + (j < 4 ? j : 12 + j);
        bia[j] = bias[n];
    }
    float s_j[8] = {}, q_j[8] = {};
#pragma unroll
    for (int i = 0; i < 8; i++) {
        int mrow = mb + (i < 4 ? i : 28 + i);
        int m = m0 + mrow;
        float vrow[8];
        unpack2(accp[i][0], vrow[0], vrow[1]);
        unpack2(accp[i][1], vrow[2], vrow[3]);
        unpack2(accp[i][2], vrow[4], vrow[5]);
        unpack2(accp[i][3], vrow[6], vrow[7]);
#pragma unroll
        for (int j = 0; j < 8; j++) {
            float v = vrow[j] + bia[j];
            vrow[j] = v;
            s_j[j] += v;
            q_j[j] += v * v;
        }
        if (WRITE_C) {
            *(float4*)(C + (size_t)m * NN + n0 + nb) =
                make_float4(vrow[0], vrow[1], vrow[2], vrow[3]);
            *(float4*)(C + (size_t)m * NN + n0 + nb + 16) =
                make_float4(vrow[4], vrow[5], vrow[6], vrow[7]);
        }
        if (MAXF) {
            int pl = m / KNN - p_base;
#pragma unroll
            for (int j = 0; j < 8; j++) {
                int c = nb + (j < 4 ? j : 12 + j);
                amax_f(&smax[pl][c], vrow[j]);
            }
        }
    }
#pragma unroll
    for (int off = 1; off < 8; off <<= 1) {
#pragma unroll
        for (int j = 0; j < 8; j++) {
            s_j[j] += __shfl_xor_sync(0xffffffffu, s_j[j], off);
            q_j[j] += __shfl_xor_sync(0xffffffffu, q_j[j], off);
        }
    }
    __syncthreads();
    if (lm == 0) {
#pragma unroll
        for (int j = 0; j < 8; j++) {
            int c = nb + (j < 4 ? j : 12 + j);
            rs[wm][c] = s_j[j];
            rq[wm][c] = q_j[j];
        }
    }
    __syncthreads();
    for (int c = tid; c < BN; c += 256) {
        float s = 0.f, q = 0.f;
#pragma unroll
        for (int w = 0; w < WM; w++) { s += rs[w][c]; q += rq[w][c]; }
        ps[(size_t)blockIdx.y * NN + n0 + c] = s;
        pq[(size_t)blockIdx.y * NN + n0 + c] = q;
    }
    if (MAXF) {
        int npts = (m0 + BM - 1) / KNN - p_base + 1;
        for (int idx = tid; idx < npts * BN; idx += 256) {
            int pl = idx / BN, c = idx % BN;
            float v = smax[pl][c];
            if (v > NEG_INF)
                amax_f(&cat[(size_t)(p_base + pl) * 512 + coff + n0 + c], v);
        }
    }
}

// ---------------- final ----------------
__global__ void final_kernel(float* __restrict__ out) {
    int i = blockIdx.x * 256 + threadIdx.x;
    int c = i & 1023;
    float v = g_sc[5][c] * g_t6[i] + g_sh[5][c];
    out[i] = v >= 0.f ? v : SLOPE * v;
}

// ---------------- launch ----------------
extern "C" void kernel_launch(void* const* d_in, const int* in_sizes, int n_in,
                              void* d_out, int out_size) {
    const float* x  = (const float*)d_in[0];
    const float* w1 = (const float*)d_in[1];
    const float* b1 = (const float*)d_in[2];
    const float* g1 = (const float*)d_in[3];
    const float* be1= (const float*)d_in[4];
    const float* w2 = (const float*)d_in[5];
    const float* b2 = (const float*)d_in[6];
    const float* g2 = (const float*)d_in[7];
    const float* be2= (const float*)d_in[8];
    const float* w3 = (const float*)d_in[9];
    const float* b3 = (const float*)d_in[10];
    const float* g3 = (const float*)d_in[11];
    const float* be3= (const float*)d_in[12];
    const float* w4 = (const float*)d_in[13];
    const float* b4 = (const float*)d_in[14];
    const float* g4 = (const float*)d_in[15];
    const float* be4= (const float*)d_in[16];
    const float* w5 = (const float*)d_in[17];
    const float* b5 = (const float*)d_in[18];
    const float* g5 = (const float*)d_in[19];
    const float* be5= (const float*)d_in[20];
    const float* w6 = (const float*)d_in[21];
    const float* b6 = (const float*)d_in[22];
    const float* g6 = (const float*)d_in[23];
    const float* be6= (const float*)d_in[24];
    float* out = (float*)d_out;

    float *t1, *t2, *t3, *t5, *t6, *cat, *scb, *shb, *csc, *csh, *ps, *pq;
    cudaGetSymbolAddress((void**)&t1, g_t1);
    cudaGetSymbolAddress((void**)&t2, g_t2);
    cudaGetSymbolAddress((void**)&t3, g_t3);
    cudaGetSymbolAddress((void**)&t5, g_t5);
    cudaGetSymbolAddress((void**)&t6, g_t6);
    cudaGetSymbolAddress((void**)&cat, g_cat);
    cudaGetSymbolAddress((void**)&scb, g_sc);
    cudaGetSymbolAddress((void**)&shb, g_sh);
    cudaGetSymbolAddress((void**)&csc, g_csc);
    cudaGetSymbolAddress((void**)&csh, g_csh);
    cudaGetSymbolAddress((void**)&ps, g_ps);
    cudaGetSymbolAddress((void**)&pq, g_pq);

    // init cat to -inf (atomic-max accumulator)
    init_cat<<<P * 512 / 256, 256>>>(cat);

    // KNN
    xx_kernel<<<P / 256, 256>>>(x);
    pd_kernel<<<dim3(16, 16, Bb), 256>>>(x);
    topk_kernel<<<P / 16, 512>>>();

    // Stage 1: decomposed conv + gather; fused stats + x1 raw max
    qp_kernel<<<dim3(16, Bb), 256>>>(x, w1);
    s1_kernel<<<P, 256>>>(b1, ps, pq, cat);
    stats_finalize<<<1, 256>>>(ps, pq, P, 64, (float)M4, 0, 0, g1, be1);

    // Stage 2: t1 -> t2 (BN1+lrelu folded); fused stats + x2 raw max
    gemm2_kernel<256, 64, true, true, true><<<dim3(1, M4 / 256), 256>>>(
        t1, w2, b2, scb + 0 * 1024, shb + 0 * 1024, t2, ps, pq, 64, 64, cat, 64);
    stats_finalize<<<1, 256>>>(ps, pq, M4 / 256, 64, (float)M4, 1, 64, g2, be2);

    // Stage 3: fused stats + x3 raw max
    gemm2_kernel<128, 128, true, true, true><<<dim3(1, M4 / 128), 256>>>(
        t2, w3, b3, scb + 1 * 1024, shb + 1 * 1024, t3, ps, pq, 64, 128, cat, 128);
    stats_finalize<<<2, 256>>>(ps, pq, M4 / 128, 128, (float)M4, 2, 128, g3, be3);

    // Stage 4: no C write at all; fused stats + x4 raw max
    gemm2_kernel<128, 128, true, false, true><<<dim3(2, M4 / 128), 256>>>(
        t3, w4, b4, scb + 2 * 1024, shb + 2 * 1024, nullptr, ps, pq, 128, 256, cat, 256);
    stats_finalize<<<4, 256>>>(ps, pq, M4 / 128, 256, (float)M4, 3, 256, g4, be4);

    // Stage 5: raw cat -> t5, folding all four stages' BN+lrelu via csc/csh
    gemm2_kernel<128, 128, true, true, false><<<dim3(2, P / 128), 256>>>(
        cat, w5, b5, csc, csh, t5, ps, pq, 512, 256, nullptr, 0);
    stats_finalize<<<4, 256>>>(ps, pq, P / 128, 256, (float)P, 4, -1, g5, be5);

    // Stage 6
    gemm2_kernel<128, 128, true, true, false><<<dim3(8, P / 128), 256>>>(
        t5, w6, b6, scb + 4 * 1024, shb + 4 * 1024, t6, ps, pq, 256, 1024, nullptr, 0);
    stats_finalize<<<16, 256>>>(ps, pq, P / 128, 1024, (float)P, 5, -1, g6, be6);

    // Final BN+lrelu -> output (B, N, 1024)
    final_kernel<<<P * 1024 / 256, 256>>>(out);
}